// round 2
// baseline (speedup 1.0000x reference)
#include <cuda_runtime.h>
#include <math.h>

#define NROWS 50000
#define DIN   1024
#define DH    512
#define DA    256
#define KSEL  8

// ---------------- scratch (static device allocations only) ----------------
__device__ float g_hh[(size_t)NROWS * DH];   // relu(fc) activations, 102.4 MB
__device__ float g_z[(size_t)NROWS * DH];    // [za | zb] pre-activations, 102.4 MB
__device__ int   g_ids[16];                  // top-8 then bottom-8 indices

// ---------------------------------------------------------------------------
// Kernel 1: hh = relu(X @ fc_W^T + fc_b)
//   X [NROWS, DIN] row-major, fc_W [DH, DIN] row-major  (NT gemm, both K-contig)
//   64x64 tile, K-chunk 16, 256 threads, 4x4 microtile   (VALIDATED in R1)
// ---------------------------------------------------------------------------
__global__ __launch_bounds__(256) void gemm1_relu_kernel(
    const float* __restrict__ X, const float* __restrict__ W,
    const float* __restrict__ bias)
{
    __shared__ float As[16][68];
    __shared__ float Bs[16][68];

    const int tid  = threadIdx.x;
    const int row0 = blockIdx.x * 64;
    const int col0 = blockIdx.y * 64;
    const int ty   = tid >> 4;
    const int tx   = tid & 15;

    const int lr = tid >> 2;
    const int lk = (tid & 3) * 4;

    float acc[4][4];
#pragma unroll
    for (int i = 0; i < 4; i++)
#pragma unroll
        for (int j = 0; j < 4; j++) acc[i][j] = 0.f;

    for (int k0 = 0; k0 < DIN; k0 += 16) {
        int arow = row0 + lr;
        float4 av = make_float4(0.f, 0.f, 0.f, 0.f);
        if (arow < NROWS)
            av = *(const float4*)&X[(size_t)arow * DIN + k0 + lk];
        As[lk + 0][lr] = av.x; As[lk + 1][lr] = av.y;
        As[lk + 2][lr] = av.z; As[lk + 3][lr] = av.w;

        float4 bv = *(const float4*)&W[(size_t)(col0 + lr) * DIN + k0 + lk];
        Bs[lk + 0][lr] = bv.x; Bs[lk + 1][lr] = bv.y;
        Bs[lk + 2][lr] = bv.z; Bs[lk + 3][lr] = bv.w;

        __syncthreads();

#pragma unroll
        for (int kk = 0; kk < 16; kk++) {
            float4 a4 = *(const float4*)&As[kk][ty * 4];
            float4 b4 = *(const float4*)&Bs[kk][tx * 4];
            float a[4] = {a4.x, a4.y, a4.z, a4.w};
            float b[4] = {b4.x, b4.y, b4.z, b4.w};
#pragma unroll
            for (int i = 0; i < 4; i++)
#pragma unroll
                for (int j = 0; j < 4; j++) acc[i][j] += a[i] * b[j];
        }
        __syncthreads();
    }

#pragma unroll
    for (int i = 0; i < 4; i++) {
        int r = row0 + ty * 4 + i;
        if (r >= NROWS) continue;
#pragma unroll
        for (int j = 0; j < 4; j++) {
            int c = col0 + tx * 4 + j;
            float v = acc[i][j] + bias[c];
            g_hh[(size_t)r * DH + c] = v > 0.f ? v : 0.f;
        }
    }
}

// ---------------------------------------------------------------------------
// Kernel 2: z = hh @ [Wa;Wb]^T  (same validated skeleton, K=DH=512, no epilogue)
//   grid.y = 8 (512 out cols / 64).  Tiles 0..3 -> Wa rows, 4..7 -> Wb rows.
// ---------------------------------------------------------------------------
__global__ __launch_bounds__(256) void gemm2_kernel(
    const float* __restrict__ Wa, const float* __restrict__ Wb)
{
    __shared__ float As[16][68];
    __shared__ float Bs[16][68];

    const int tid  = threadIdx.x;
    const int row0 = blockIdx.x * 64;
    const int col0 = blockIdx.y * 64;      // 0..448
    const float* W  = (col0 < DA) ? Wa : Wb;
    const int wcol0 = (col0 < DA) ? col0 : col0 - DA;

    const int ty = tid >> 4;
    const int tx = tid & 15;
    const int lr = tid >> 2;
    const int lk = (tid & 3) * 4;

    float acc[4][4];
#pragma unroll
    for (int i = 0; i < 4; i++)
#pragma unroll
        for (int j = 0; j < 4; j++) acc[i][j] = 0.f;

    for (int k0 = 0; k0 < DH; k0 += 16) {
        int arow = row0 + lr;
        float4 av = make_float4(0.f, 0.f, 0.f, 0.f);
        if (arow < NROWS)
            av = *(const float4*)&g_hh[(size_t)arow * DH + k0 + lk];
        As[lk + 0][lr] = av.x; As[lk + 1][lr] = av.y;
        As[lk + 2][lr] = av.z; As[lk + 3][lr] = av.w;

        float4 bv = *(const float4*)&W[(size_t)(wcol0 + lr) * DH + k0 + lk];
        Bs[lk + 0][lr] = bv.x; Bs[lk + 1][lr] = bv.y;
        Bs[lk + 2][lr] = bv.z; Bs[lk + 3][lr] = bv.w;

        __syncthreads();

#pragma unroll
        for (int kk = 0; kk < 16; kk++) {
            float4 a4 = *(const float4*)&As[kk][ty * 4];
            float4 b4 = *(const float4*)&Bs[kk][tx * 4];
            float a[4] = {a4.x, a4.y, a4.z, a4.w};
            float b[4] = {b4.x, b4.y, b4.z, b4.w};
#pragma unroll
            for (int i = 0; i < 4; i++)
#pragma unroll
                for (int j = 0; j < 4; j++) acc[i][j] += a[i] * b[j];
        }
        __syncthreads();
    }

#pragma unroll
    for (int i = 0; i < 4; i++) {
        int r = row0 + ty * 4 + i;
        if (r >= NROWS) continue;
#pragma unroll
        for (int j = 0; j < 4; j++) {
            int c = col0 + tx * 4 + j;
            g_z[(size_t)r * DH + c] = acc[i][j];
        }
    }
}

// ---------------------------------------------------------------------------
// Kernel 2b: A_raw[n] = sum_j cW[j]*tanh(z[n,j]+ab[j])*sigmoid(z[n,j+256]+bb[j]) + cb
//   one warp per row
// ---------------------------------------------------------------------------
__global__ __launch_bounds__(256) void araw_kernel(
    const float* __restrict__ ab, const float* __restrict__ bb,
    const float* __restrict__ cW, const float* __restrict__ cb,
    float* __restrict__ Araw)
{
    int row  = (blockIdx.x * blockDim.x + threadIdx.x) >> 5;
    int lane = threadIdx.x & 31;
    if (row >= NROWS) return;
    const float* zr = &g_z[(size_t)row * DH];
    float s = 0.f;
#pragma unroll
    for (int j = lane; j < DA; j += 32) {
        float za = zr[j]      + ab[j];
        float zb = zr[j + DA] + bb[j];
        float av = tanhf(za);
        float bv = 1.f / (1.f + expf(-zb));
        s += cW[j] * av * bv;
    }
#pragma unroll
    for (int m = 16; m > 0; m >>= 1) s += __shfl_xor_sync(0xffffffffu, s, m);
    if (lane == 0) Araw[row] = s + cb[0];
}

// ---------------------------------------------------------------------------
// Kernel 3: instance_scores = hh @ cls_W^T + cls_b   ([NROWS, 2])
// ---------------------------------------------------------------------------
__global__ __launch_bounds__(256) void cls_kernel(
    const float* __restrict__ clsW, const float* __restrict__ clsb,
    float* __restrict__ IS)
{
    int gw   = (blockIdx.x * blockDim.x + threadIdx.x) >> 5;
    int lane = threadIdx.x & 31;
    if (gw >= NROWS) return;
    const float* hr = &g_hh[(size_t)gw * DH];
    float c0 = 0.f, c1 = 0.f;
    for (int k = lane * 4; k < DH; k += 128) {
        float4 h  = *(const float4*)&hr[k];
        float4 w0 = *(const float4*)&clsW[k];
        float4 w1 = *(const float4*)&clsW[DH + k];
        c0 += h.x * w0.x + h.y * w0.y + h.z * w0.z + h.w * w0.w;
        c1 += h.x * w1.x + h.y * w1.y + h.z * w1.z + h.w * w1.w;
    }
#pragma unroll
    for (int m = 16; m > 0; m >>= 1) {
        c0 += __shfl_xor_sync(0xffffffffu, c0, m);
        c1 += __shfl_xor_sync(0xffffffffu, c1, m);
    }
    if (lane == 0) {
        IS[(size_t)gw * 2 + 0] = c0 + clsb[0];
        IS[(size_t)gw * 2 + 1] = c1 + clsb[1];
    }
}

// ---------------------------------------------------------------------------
// Kernel 4: softmax-weighted pooled preds (single block, deterministic)
// ---------------------------------------------------------------------------
__global__ __launch_bounds__(1024) void preds_kernel(
    const float* __restrict__ Araw, const float* __restrict__ IS,
    float* __restrict__ preds)
{
    __shared__ float r0[1024];
    __shared__ float r1[1024];
    __shared__ float r2[1024];
    int tid = threadIdx.x;

    float m = -INFINITY;
    for (int n = tid; n < NROWS; n += 1024) m = fmaxf(m, Araw[n]);
    r0[tid] = m;
    __syncthreads();
    for (int s = 512; s > 0; s >>= 1) {
        if (tid < s) r0[tid] = fmaxf(r0[tid], r0[tid + s]);
        __syncthreads();
    }
    m = r0[0];
    __syncthreads();

    float s0 = 0.f, p0 = 0.f, p1 = 0.f;
    for (int n = tid; n < NROWS; n += 1024) {
        float e = expf(Araw[n] - m);
        s0 += e;
        p0 += e * IS[(size_t)n * 2 + 0];
        p1 += e * IS[(size_t)n * 2 + 1];
    }
    r0[tid] = s0; r1[tid] = p0; r2[tid] = p1;
    __syncthreads();
    for (int s = 512; s > 0; s >>= 1) {
        if (tid < s) {
            r0[tid] += r0[tid + s];
            r1[tid] += r1[tid + s];
            r2[tid] += r2[tid + s];
        }
        __syncthreads();
    }
    if (tid == 0) {
        preds[0] = r1[0] / r0[0];
        preds[1] = r2[0] / r0[0];
    }
}

// ---------------------------------------------------------------------------
// Kernel 5: top-8 / bottom-8 selection (deterministic, ties -> lower index)
// ---------------------------------------------------------------------------
__global__ __launch_bounds__(1024) void topk_kernel(const float* __restrict__ Araw)
{
    __shared__ float sv[1024];
    __shared__ int   si[1024];
    __shared__ int   sel[16];
    int tid = threadIdx.x;

    for (int it = 0; it < 16; it++) {
        bool mx = (it < KSEL);
        float bk = -INFINITY;
        int bi = 0x7fffffff;
        for (int n = tid; n < NROWS; n += 1024) {
            bool skip = false;
            for (int p = 0; p < it; p++)
                if (sel[p] == n) { skip = true; }
            if (skip) continue;
            float v = Araw[n];
            float key = mx ? v : -v;
            if (key > bk || (key == bk && n < bi)) { bk = key; bi = n; }
        }
        sv[tid] = bk; si[tid] = bi;
        __syncthreads();
        for (int s = 512; s > 0; s >>= 1) {
            if (tid < s) {
                if (sv[tid + s] > sv[tid] ||
                    (sv[tid + s] == sv[tid] && si[tid + s] < si[tid])) {
                    sv[tid] = sv[tid + s];
                    si[tid] = si[tid + s];
                }
            }
            __syncthreads();
        }
        if (tid == 0) { sel[it] = si[0]; g_ids[it] = si[0]; }
        __syncthreads();
    }
}

// ---------------------------------------------------------------------------
// Kernel 6: instance loss (16 selected rows, 1 warp each)
// ---------------------------------------------------------------------------
__global__ __launch_bounds__(512) void loss_kernel(
    const float* __restrict__ iW, const float* __restrict__ ib,
    float* __restrict__ loss)
{
    __shared__ float ls[16];
    int w    = threadIdx.x >> 5;
    int lane = threadIdx.x & 31;
    int id   = g_ids[w];
    const float* hr = &g_hh[(size_t)id * DH];
    float c0 = 0.f, c1 = 0.f;
    for (int k = lane * 4; k < DH; k += 128) {
        float4 h  = *(const float4*)&hr[k];
        float4 w0 = *(const float4*)&iW[k];
        float4 w1 = *(const float4*)&iW[DH + k];
        c0 += h.x * w0.x + h.y * w0.y + h.z * w0.z + h.w * w0.w;
        c1 += h.x * w1.x + h.y * w1.y + h.z * w1.z + h.w * w1.w;
    }
#pragma unroll
    for (int m = 16; m > 0; m >>= 1) {
        c0 += __shfl_xor_sync(0xffffffffu, c0, m);
        c1 += __shfl_xor_sync(0xffffffffu, c1, m);
    }
    if (lane == 0) {
        float l0 = c0 + ib[0], l1 = c1 + ib[1];
        float mm  = fmaxf(l0, l1);
        float lse = mm + logf(expf(l0 - mm) + expf(l1 - mm));
        float lt  = (w < KSEL) ? l1 : l0;   // top rows -> class 1, bottom -> class 0
        ls[w] = lse - lt;                   // = -logp[target]
    }
    __syncthreads();
    if (threadIdx.x == 0) {
        float t = 0.f;
        for (int i = 0; i < 16; i++) t += ls[i];
        loss[0] = t / 16.f;
    }
}

// ---------------------------------------------------------------------------
extern "C" void kernel_launch(void* const* d_in, const int* in_sizes, int n_in,
                              void* d_out, int out_size)
{
    const float* h     = (const float*)d_in[0];
    const float* fcW   = (const float*)d_in[1];
    const float* fcb   = (const float*)d_in[2];
    const float* aW    = (const float*)d_in[3];
    const float* abv   = (const float*)d_in[4];
    const float* bW    = (const float*)d_in[5];
    const float* bbv   = (const float*)d_in[6];
    const float* cWv   = (const float*)d_in[7];
    const float* cbv   = (const float*)d_in[8];
    const float* clsW  = (const float*)d_in[9];
    const float* clsb  = (const float*)d_in[10];
    const float* instW = (const float*)d_in[11];
    const float* instb = (const float*)d_in[12];

    float* out   = (float*)d_out;
    float* preds = out;                       // [2]
    float* IS    = out + 2;                   // [NROWS*2]
    float* Araw  = out + 2 + 2 * NROWS;       // [NROWS]
    float* loss  = out + 2 + 3 * NROWS;       // [1]

    dim3 g1((NROWS + 63) / 64, DIN ? DH / 64 : 0);
    gemm1_relu_kernel<<<g1, 256>>>(h, fcW, fcb);

    dim3 g2((NROWS + 63) / 64, DH / 64);      // 8 col tiles (4 Wa + 4 Wb)
    gemm2_kernel<<<g2, 256>>>(aW, bW);

    araw_kernel<<<(NROWS * 32 + 255) / 256, 256>>>(abv, bbv, cWv, cbv, Araw);

    cls_kernel<<<(NROWS * 32 + 255) / 256, 256>>>(clsW, clsb, IS);

    preds_kernel<<<1, 1024>>>(Araw, IS, preds);

    topk_kernel<<<1, 1024>>>(Araw);

    loss_kernel<<<1, 512>>>(instW, instb, loss);
}

// round 4
// speedup vs baseline: 1.8780x; 1.8780x over previous
#include <cuda_runtime.h>
#include <cuda_bf16.h>
#include <math.h>
#include <stdint.h>

#define NROWS 50000
#define DIN   1024
#define DH    512
#define DA    256
#define KSEL  8

#define BM 128
#define BN 128
#define BK 32
#define SSTR 40   // smem row stride in bf16 (32 + 8 pad) -> conflict-free frags

// ---------------- scratch (static device allocations only) ----------------
__device__ float g_hh[(size_t)NROWS * DH];   // relu(fc) activations
__device__ float g_z[(size_t)NROWS * DH];    // [za | zb]
__device__ int   g_ids[16];

// ---------------------------------------------------------------------------
// bf16 split helper: x = hi + lo (both bf16), exact to ~2^-16 relative
// ---------------------------------------------------------------------------
__device__ __forceinline__ void split2(float x, float y, uint32_t& hi, uint32_t& lo)
{
    __nv_bfloat16 hx = __float2bfloat16(x);
    __nv_bfloat16 hy = __float2bfloat16(y);
    __nv_bfloat16 lx = __float2bfloat16(x - __bfloat162float(hx));
    __nv_bfloat16 ly = __float2bfloat16(y - __bfloat162float(hy));
    hi = (uint32_t)__bfloat16_as_ushort(hx) | ((uint32_t)__bfloat16_as_ushort(hy) << 16);
    lo = (uint32_t)__bfloat16_as_ushort(lx) | ((uint32_t)__bfloat16_as_ushort(ly) << 16);
}

__device__ __forceinline__ void mma_bf16(float* d, const uint32_t* a, const uint32_t* b)
{
    asm volatile(
        "mma.sync.aligned.m16n8k16.row.col.f32.bf16.bf16.f32 "
        "{%0,%1,%2,%3}, {%4,%5,%6,%7}, {%8,%9}, {%0,%1,%2,%3};"
        : "+f"(d[0]), "+f"(d[1]), "+f"(d[2]), "+f"(d[3])
        : "r"(a[0]), "r"(a[1]), "r"(a[2]), "r"(a[3]), "r"(b[0]), "r"(b[1]));
}

// ===========================================================================
// 3xBF16 split GEMM:  C[M, 512] = A[M, K] @ B[512, K]^T   (fp32 in/out)
//   B rows n < splitN come from B0, else B1 (row n-splitN)  (for [Wa;Wb])
//   mode 0: C = relu(C + bias) -> Cf ;  mode 1: C -> Cf raw
// ===========================================================================
__global__ __launch_bounds__(256, 2) void gemm_mma_kernel(
    const float* __restrict__ A,
    const float* __restrict__ B0, const float* __restrict__ B1, int splitN,
    const float* __restrict__ bias, int K, int mode, float* __restrict__ Cf)
{
    __shared__ __nv_bfloat16 sAhi[BM * SSTR];
    __shared__ __nv_bfloat16 sAlo[BM * SSTR];
    __shared__ __nv_bfloat16 sBhi[BN * SSTR];
    __shared__ __nv_bfloat16 sBlo[BN * SSTR];

    const int tid    = threadIdx.x;
    const int wid    = tid >> 5;
    const int lane   = tid & 31;
    const int warp_m = wid & 1;        // 0..1  (64 rows each)
    const int warp_n = wid >> 1;       // 0..3  (32 cols each)
    const int g      = lane >> 2;      // 0..7
    const int t      = lane & 3;       // 0..3
    const int row0   = blockIdx.x * BM;
    const int col0   = blockIdx.y * BN;

    float acc[4][4][4];
#pragma unroll
    for (int mt = 0; mt < 4; mt++)
#pragma unroll
        for (int nt = 0; nt < 4; nt++)
#pragma unroll
            for (int e = 0; e < 4; e++) acc[mt][nt][e] = 0.f;

    for (int k0 = 0; k0 < K; k0 += BK) {
        // ---- fill A hi/lo: 128 rows x 32 cols, 4 float4 per thread ----
#pragma unroll
        for (int i = 0; i < 4; i++) {
            int f   = tid + 256 * i;
            int r   = f >> 3;
            int cq  = (f & 7) * 4;
            int gr  = row0 + r;
            float4 v = make_float4(0.f, 0.f, 0.f, 0.f);
            if (gr < NROWS) v = *(const float4*)&A[(size_t)gr * K + k0 + cq];
            uint32_t h0, l0, h1, l1;
            split2(v.x, v.y, h0, l0);
            split2(v.z, v.w, h1, l1);
            uint2 ph = make_uint2(h0, h1), pl = make_uint2(l0, l1);
            *(uint2*)&sAhi[r * SSTR + cq] = ph;
            *(uint2*)&sAlo[r * SSTR + cq] = pl;
        }
        // ---- fill B hi/lo ----
#pragma unroll
        for (int i = 0; i < 4; i++) {
            int f  = tid + 256 * i;
            int r  = f >> 3;
            int cq = (f & 7) * 4;
            int n  = col0 + r;
            const float* src = (n < splitN) ? &B0[(size_t)n * K + k0 + cq]
                                            : &B1[(size_t)(n - splitN) * K + k0 + cq];
            float4 v = *(const float4*)src;
            uint32_t h0, l0, h1, l1;
            split2(v.x, v.y, h0, l0);
            split2(v.z, v.w, h1, l1);
            *(uint2*)&sBhi[r * SSTR + cq] = make_uint2(h0, h1);
            *(uint2*)&sBlo[r * SSTR + cq] = make_uint2(l0, l1);
        }
        __syncthreads();

#pragma unroll
        for (int ks = 0; ks < BK; ks += 16) {
            // B fragments for this warp's 4 n8 tiles
            uint32_t bh[4][2], bl[4][2];
#pragma unroll
            for (int nt = 0; nt < 4; nt++) {
                int nb = warp_n * 32 + nt * 8 + g;
                bh[nt][0] = *(const uint32_t*)&sBhi[nb * SSTR + ks + 2 * t];
                bh[nt][1] = *(const uint32_t*)&sBhi[nb * SSTR + ks + 8 + 2 * t];
                bl[nt][0] = *(const uint32_t*)&sBlo[nb * SSTR + ks + 2 * t];
                bl[nt][1] = *(const uint32_t*)&sBlo[nb * SSTR + ks + 8 + 2 * t];
            }
#pragma unroll
            for (int mt = 0; mt < 4; mt++) {
                int rb = warp_m * 64 + mt * 16;
                uint32_t ah[4], al[4];
                ah[0] = *(const uint32_t*)&sAhi[(rb + g) * SSTR + ks + 2 * t];
                ah[1] = *(const uint32_t*)&sAhi[(rb + g + 8) * SSTR + ks + 2 * t];
                ah[2] = *(const uint32_t*)&sAhi[(rb + g) * SSTR + ks + 8 + 2 * t];
                ah[3] = *(const uint32_t*)&sAhi[(rb + g + 8) * SSTR + ks + 8 + 2 * t];
                al[0] = *(const uint32_t*)&sAlo[(rb + g) * SSTR + ks + 2 * t];
                al[1] = *(const uint32_t*)&sAlo[(rb + g + 8) * SSTR + ks + 2 * t];
                al[2] = *(const uint32_t*)&sAlo[(rb + g) * SSTR + ks + 8 + 2 * t];
                al[3] = *(const uint32_t*)&sAlo[(rb + g + 8) * SSTR + ks + 8 + 2 * t];
#pragma unroll
                for (int nt = 0; nt < 4; nt++) {
                    mma_bf16(acc[mt][nt], ah, bh[nt]);   // hi*hi
                    mma_bf16(acc[mt][nt], ah, bl[nt]);   // hi*lo
                    mma_bf16(acc[mt][nt], al, bh[nt]);   // lo*hi
                }
            }
        }
        __syncthreads();
    }

    // ---- epilogue: fragment -> gmem ----
#pragma unroll
    for (int mt = 0; mt < 4; mt++) {
        int r0 = row0 + warp_m * 64 + mt * 16 + g;
        int r1 = r0 + 8;
#pragma unroll
        for (int nt = 0; nt < 4; nt++) {
            int c = col0 + warp_n * 32 + nt * 8 + 2 * t;
            float v0 = acc[mt][nt][0], v1 = acc[mt][nt][1];
            float v2 = acc[mt][nt][2], v3 = acc[mt][nt][3];
            if (mode == 0) {
                float b0 = __ldg(&bias[c]), b1 = __ldg(&bias[c + 1]);
                v0 = fmaxf(v0 + b0, 0.f); v1 = fmaxf(v1 + b1, 0.f);
                v2 = fmaxf(v2 + b0, 0.f); v3 = fmaxf(v3 + b1, 0.f);
            }
            if (r0 < NROWS) *(float2*)&Cf[(size_t)r0 * DH + c] = make_float2(v0, v1);
            if (r1 < NROWS) *(float2*)&Cf[(size_t)r1 * DH + c] = make_float2(v2, v3);
        }
    }
}

// ---------------------------------------------------------------------------
// A_raw[n] = sum_j cW[j]*tanh(z[n,j]+ab[j])*sigmoid(z[n,j+256]+bb[j]) + cb
// ---------------------------------------------------------------------------
__global__ __launch_bounds__(256) void araw_kernel(
    const float* __restrict__ ab, const float* __restrict__ bb,
    const float* __restrict__ cW, const float* __restrict__ cb,
    float* __restrict__ Araw)
{
    int row  = (blockIdx.x * blockDim.x + threadIdx.x) >> 5;
    int lane = threadIdx.x & 31;
    if (row >= NROWS) return;
    const float* zr = &g_z[(size_t)row * DH];
    float s = 0.f;
#pragma unroll
    for (int j = lane; j < DA; j += 32) {
        float za = zr[j]      + ab[j];
        float zb = zr[j + DA] + bb[j];
        float av = tanhf(za);
        float bv = 1.f / (1.f + expf(-zb));
        s += cW[j] * av * bv;
    }
#pragma unroll
    for (int m = 16; m > 0; m >>= 1) s += __shfl_xor_sync(0xffffffffu, s, m);
    if (lane == 0) Araw[row] = s + cb[0];
}

// ---------------------------------------------------------------------------
// instance_scores = hh @ cls_W^T + cls_b
// ---------------------------------------------------------------------------
__global__ __launch_bounds__(256) void cls_kernel(
    const float* __restrict__ clsW, const float* __restrict__ clsb,
    float* __restrict__ IS)
{
    int gw   = (blockIdx.x * blockDim.x + threadIdx.x) >> 5;
    int lane = threadIdx.x & 31;
    if (gw >= NROWS) return;
    const float* hr = &g_hh[(size_t)gw * DH];
    float c0 = 0.f, c1 = 0.f;
    for (int k = lane * 4; k < DH; k += 128) {
        float4 h  = *(const float4*)&hr[k];
        float4 w0 = *(const float4*)&clsW[k];
        float4 w1 = *(const float4*)&clsW[DH + k];
        c0 += h.x * w0.x + h.y * w0.y + h.z * w0.z + h.w * w0.w;
        c1 += h.x * w1.x + h.y * w1.y + h.z * w1.z + h.w * w1.w;
    }
#pragma unroll
    for (int m = 16; m > 0; m >>= 1) {
        c0 += __shfl_xor_sync(0xffffffffu, c0, m);
        c1 += __shfl_xor_sync(0xffffffffu, c1, m);
    }
    if (lane == 0) {
        IS[(size_t)gw * 2 + 0] = c0 + clsb[0];
        IS[(size_t)gw * 2 + 1] = c1 + clsb[1];
    }
}

// ---------------------------------------------------------------------------
// softmax-weighted pooled preds (single block, deterministic)
// ---------------------------------------------------------------------------
__global__ __launch_bounds__(1024) void preds_kernel(
    const float* __restrict__ Araw, const float* __restrict__ IS,
    float* __restrict__ preds)
{
    __shared__ float r0[1024];
    __shared__ float r1[1024];
    __shared__ float r2[1024];
    int tid = threadIdx.x;

    float m = -INFINITY;
    for (int n = tid; n < NROWS; n += 1024) m = fmaxf(m, Araw[n]);
    r0[tid] = m;
    __syncthreads();
    for (int s = 512; s > 0; s >>= 1) {
        if (tid < s) r0[tid] = fmaxf(r0[tid], r0[tid + s]);
        __syncthreads();
    }
    m = r0[0];
    __syncthreads();

    float s0 = 0.f, p0 = 0.f, p1 = 0.f;
    for (int n = tid; n < NROWS; n += 1024) {
        float e = expf(Araw[n] - m);
        s0 += e;
        p0 += e * IS[(size_t)n * 2 + 0];
        p1 += e * IS[(size_t)n * 2 + 1];
    }
    r0[tid] = s0; r1[tid] = p0; r2[tid] = p1;
    __syncthreads();
    for (int s = 512; s > 0; s >>= 1) {
        if (tid < s) {
            r0[tid] += r0[tid + s];
            r1[tid] += r1[tid + s];
            r2[tid] += r2[tid + s];
        }
        __syncthreads();
    }
    if (tid == 0) {
        preds[0] = r1[0] / r0[0];
        preds[1] = r2[0] / r0[0];
    }
}

// ---------------------------------------------------------------------------
// top-8 / bottom-8, single data pass + pool extraction (ties -> lower index)
// ---------------------------------------------------------------------------
__global__ __launch_bounds__(512) void topk_kernel(const float* __restrict__ Araw)
{
    __shared__ float pv[512 * 8];
    __shared__ int   pi[512 * 8];
    __shared__ float sv[512];
    __shared__ int   si[512];
    __shared__ int   sp[512];
    int tid = threadIdx.x;

    for (int pass = 0; pass < 2; pass++) {
        bool mx = (pass == 0);
        float tv[8];
        int   ti[8];
#pragma unroll
        for (int j = 0; j < 8; j++) { tv[j] = mx ? -INFINITY : INFINITY; ti[j] = 0x7fffffff; }
        for (int n = tid; n < NROWS; n += 512) {
            float v = Araw[n];
            bool better_last = mx ? (v > tv[7] || (v == tv[7] && n < ti[7]))
                                  : (v < tv[7] || (v == tv[7] && n < ti[7]));
            if (better_last) {
                int p = 7;
#pragma unroll
                for (int q = 7; q > 0; q--) {
                    bool up = mx ? (v > tv[q - 1] || (v == tv[q - 1] && n < ti[q - 1]))
                                 : (v < tv[q - 1] || (v == tv[q - 1] && n < ti[q - 1]));
                    if (up) { tv[q] = tv[q - 1]; ti[q] = ti[q - 1]; p = q - 1; }
                }
                tv[p] = v; ti[p] = n;
            }
        }
#pragma unroll
        for (int j = 0; j < 8; j++) { pv[tid * 8 + j] = tv[j]; pi[tid * 8 + j] = ti[j]; }
        __syncthreads();

        for (int it = 0; it < 8; it++) {
            float bk = mx ? -INFINITY : INFINITY;
            int bi = 0x7fffffff, bp = -1;
            for (int e = tid; e < 512 * 8; e += 512) {
                float v = pv[e];
                int   n = pi[e];
                bool better = mx ? (v > bk || (v == bk && n < bi))
                                 : (v < bk || (v == bk && n < bi));
                if (better) { bk = v; bi = n; bp = e; }
            }
            sv[tid] = bk; si[tid] = bi; sp[tid] = bp;
            __syncthreads();
            for (int s = 256; s > 0; s >>= 1) {
                if (tid < s) {
                    bool better = mx ? (sv[tid + s] > sv[tid] ||
                                        (sv[tid + s] == sv[tid] && si[tid + s] < si[tid]))
                                     : (sv[tid + s] < sv[tid] ||
                                        (sv[tid + s] == sv[tid] && si[tid + s] < si[tid]));
                    if (better) { sv[tid] = sv[tid + s]; si[tid] = si[tid + s]; sp[tid] = sp[tid + s]; }
                }
                __syncthreads();
            }
            if (tid == 0) {
                g_ids[pass * 8 + it] = si[0];
                pv[sp[0]] = mx ? -INFINITY : INFINITY;
                pi[sp[0]] = 0x7fffffff;
            }
            __syncthreads();
        }
        __syncthreads();
    }
}

// ---------------------------------------------------------------------------
// instance loss (16 selected rows, 1 warp each)
// ---------------------------------------------------------------------------
__global__ __launch_bounds__(512) void loss_kernel(
    const float* __restrict__ iW, const float* __restrict__ ib,
    float* __restrict__ loss)
{
    __shared__ float ls[16];
    int w    = threadIdx.x >> 5;
    int lane = threadIdx.x & 31;
    int id   = g_ids[w];
    const float* hr = &g_hh[(size_t)id * DH];
    float c0 = 0.f, c1 = 0.f;
    for (int k = lane * 4; k < DH; k += 128) {
        float4 h  = *(const float4*)&hr[k];
        float4 w0 = *(const float4*)&iW[k];
        float4 w1 = *(const float4*)&iW[DH + k];
        c0 += h.x * w0.x + h.y * w0.y + h.z * w0.z + h.w * w0.w;
        c1 += h.x * w1.x + h.y * w1.y + h.z * w1.z + h.w * w1.w;
    }
#pragma unroll
    for (int m = 16; m > 0; m >>= 1) {
        c0 += __shfl_xor_sync(0xffffffffu, c0, m);
        c1 += __shfl_xor_sync(0xffffffffu, c1, m);
    }
    if (lane == 0) {
        float l0 = c0 + ib[0], l1 = c1 + ib[1];
        float mm  = fmaxf(l0, l1);
        float lse = mm + logf(expf(l0 - mm) + expf(l1 - mm));
        float lt  = (w < KSEL) ? l1 : l0;
        ls[w] = lse - lt;
    }
    __syncthreads();
    if (threadIdx.x == 0) {
        float t = 0.f;
        for (int i = 0; i < 16; i++) t += ls[i];
        loss[0] = t / 16.f;
    }
}

// ---------------------------------------------------------------------------
extern "C" void kernel_launch(void* const* d_in, const int* in_sizes, int n_in,
                              void* d_out, int out_size)
{
    const float* h     = (const float*)d_in[0];
    const float* fcW   = (const float*)d_in[1];
    const float* fcb   = (const float*)d_in[2];
    const float* aW    = (const float*)d_in[3];
    const float* abv   = (const float*)d_in[4];
    const float* bW    = (const float*)d_in[5];
    const float* bbv   = (const float*)d_in[6];
    const float* cWv   = (const float*)d_in[7];
    const float* cbv   = (const float*)d_in[8];
    const float* clsW  = (const float*)d_in[9];
    const float* clsb  = (const float*)d_in[10];
    const float* instW = (const float*)d_in[11];
    const float* instb = (const float*)d_in[12];

    float* out   = (float*)d_out;
    float* preds = out;
    float* IS    = out + 2;
    float* Araw  = out + 2 + 2 * NROWS;
    float* loss  = out + 2 + 3 * NROWS;

    float *hhf, *zf;
    cudaGetSymbolAddress((void**)&hhf, g_hh);
    cudaGetSymbolAddress((void**)&zf,  g_z);

    dim3 grid((NROWS + BM - 1) / BM, DH / BN);   // (391, 4)

    // gemm1: hh = relu(X @ fcW^T + fcb)
    gemm_mma_kernel<<<grid, 256>>>(h, fcW, fcW, DH, fcb, DIN, 0, hhf);

    // gemm2: z = hh @ [Wa;Wb]^T
    gemm_mma_kernel<<<grid, 256>>>(hhf, aW, bW, DA, fcb, DH, 1, zf);

    araw_kernel<<<(NROWS * 32 + 255) / 256, 256>>>(abv, bbv, cWv, cbv, Araw);

    cls_kernel<<<(NROWS * 32 + 255) / 256, 256>>>(clsW, clsb, IS);

    preds_kernel<<<1, 1024>>>(Araw, IS, preds);

    topk_kernel<<<1, 512>>>(Araw);

    loss_kernel<<<1, 512>>>(instW, instb, loss);
}

// round 5
// speedup vs baseline: 2.6409x; 1.4062x over previous
#include <cuda_runtime.h>
#include <cuda_bf16.h>
#include <math.h>
#include <stdint.h>

#define NROWS 50000
#define DIN   1024
#define DH    512
#define DA    256
#define KSEL  8

#define BM 128
#define BN 128
#define BK 32

// smem layout (bytes): per stage: Ahi, Alo (128 rows x 80B), Bhi, Blo
#define ROWB      80            // 40 bf16 stride (32 data + 8 pad) -> LDSM conflict-free
#define OFF_AHI   0
#define OFF_ALO   10240
#define OFF_BHI   20480
#define OFF_BLO   30720
#define STAGEB    40960
#define SMEM_GEMM (2 * STAGEB)  // 81920

// ---------------- scratch (static device allocations only) ----------------
__device__ float          g_hh[(size_t)NROWS * DH];
__device__ float          g_z[(size_t)NROWS * DH];
__device__ __nv_bfloat16  g_x_hi[(size_t)NROWS * DIN];
__device__ __nv_bfloat16  g_x_lo[(size_t)NROWS * DIN];
__device__ __nv_bfloat16  g_hh_hi[(size_t)NROWS * DH];
__device__ __nv_bfloat16  g_hh_lo[(size_t)NROWS * DH];
__device__ __nv_bfloat16  g_w1_hi[(size_t)DH * DIN];
__device__ __nv_bfloat16  g_w1_lo[(size_t)DH * DIN];
__device__ __nv_bfloat16  g_wab_hi[(size_t)DH * DH];   // rows 0..255 Wa, 256..511 Wb
__device__ __nv_bfloat16  g_wab_lo[(size_t)DH * DH];
__device__ int            g_ids[16];

// ============================ helpers ======================================
__device__ __forceinline__ uint32_t smem_u32(const void* p) {
    uint32_t a;
    asm("{ .reg .u64 t; cvta.to.shared.u64 t, %1; cvt.u32.u64 %0, t; }" : "=r"(a) : "l"(p));
    return a;
}
__device__ __forceinline__ void split2(float x, float y, uint32_t& hi, uint32_t& lo)
{
    __nv_bfloat16 hx = __float2bfloat16(x);
    __nv_bfloat16 hy = __float2bfloat16(y);
    __nv_bfloat16 lx = __float2bfloat16(x - __bfloat162float(hx));
    __nv_bfloat16 ly = __float2bfloat16(y - __bfloat162float(hy));
    hi = (uint32_t)__bfloat16_as_ushort(hx) | ((uint32_t)__bfloat16_as_ushort(hy) << 16);
    lo = (uint32_t)__bfloat16_as_ushort(lx) | ((uint32_t)__bfloat16_as_ushort(ly) << 16);
}
__device__ __forceinline__ void mma_bf16(float* d, const uint32_t* a, const uint32_t* b)
{
    asm volatile(
        "mma.sync.aligned.m16n8k16.row.col.f32.bf16.bf16.f32 "
        "{%0,%1,%2,%3}, {%4,%5,%6,%7}, {%8,%9}, {%0,%1,%2,%3};"
        : "+f"(d[0]), "+f"(d[1]), "+f"(d[2]), "+f"(d[3])
        : "r"(a[0]), "r"(a[1]), "r"(a[2]), "r"(a[3]), "r"(b[0]), "r"(b[1]));
}
#define LDSM_X4(r0, r1, r2, r3, addr) \
    asm volatile("ldmatrix.sync.aligned.m8n8.x4.shared.b16 {%0,%1,%2,%3}, [%4];" \
                 : "=r"(r0), "=r"(r1), "=r"(r2), "=r"(r3) : "r"(addr))
#define CP_ASYNC16(dst, src, sz) \
    asm volatile("cp.async.cg.shared.global [%0], [%1], 16, %2;" \
                 :: "r"(dst), "l"(src), "r"(sz))
#define CP_COMMIT()  asm volatile("cp.async.commit_group;" ::: "memory")
#define CP_WAIT(n)   asm volatile("cp.async.wait_group %0;" :: "n"(n) : "memory")

// ============================ convert kernels ==============================
__global__ __launch_bounds__(256) void conv_split_kernel(
    const float* __restrict__ src, __nv_bfloat16* __restrict__ hi,
    __nv_bfloat16* __restrict__ lo, int n4)
{
    int i = blockIdx.x * blockDim.x + threadIdx.x;
    if (i >= n4) return;
    float4 v = ((const float4*)src)[i];
    uint32_t h0, l0, h1, l1;
    split2(v.x, v.y, h0, l0);
    split2(v.z, v.w, h1, l1);
    ((uint2*)hi)[i] = make_uint2(h0, h1);
    ((uint2*)lo)[i] = make_uint2(l0, l1);
}

__global__ __launch_bounds__(256) void conv_wab_kernel(
    const float* __restrict__ Wa, const float* __restrict__ Wb)
{
    int i = blockIdx.x * blockDim.x + threadIdx.x;
    if (i >= DH * DH / 4) return;
    int elem = i * 4;
    int row = elem / DH;
    int col = elem % DH;
    const float* src = (row < DA) ? &Wa[(size_t)row * DH + col]
                                  : &Wb[(size_t)(row - DA) * DH + col];
    float4 v = *(const float4*)src;
    uint32_t h0, l0, h1, l1;
    split2(v.x, v.y, h0, l0);
    split2(v.z, v.w, h1, l1);
    ((uint2*)g_wab_hi)[i] = make_uint2(h0, h1);
    ((uint2*)g_wab_lo)[i] = make_uint2(l0, l1);
}

// ===========================================================================
// 3xBF16 split GEMM via mma.sync + ldmatrix + cp.async double buffering
//   C[M, 512] = A[M, K] @ B[512, K]^T ; A/B given as bf16 hi/lo pairs
//   mode 0: relu(C + bias) -> Cf fp32 AND Chi/Clo bf16 split
//   mode 1: C -> Cf
// ===========================================================================
__global__ __launch_bounds__(256, 2) void gemm_mma_kernel(
    const __nv_bfloat16* __restrict__ Ahi, const __nv_bfloat16* __restrict__ Alo,
    const __nv_bfloat16* __restrict__ Bhi, const __nv_bfloat16* __restrict__ Blo,
    const float* __restrict__ bias, int K, int mode, float* __restrict__ Cf,
    __nv_bfloat16* __restrict__ Chi, __nv_bfloat16* __restrict__ Clo)
{
    extern __shared__ char smem[];
    const uint32_t sbase = smem_u32(smem);

    const int tid    = threadIdx.x;
    const int wid    = tid >> 5;
    const int lane   = tid & 31;
    const int warp_m = wid & 1;
    const int warp_n = wid >> 1;
    const int g      = lane >> 2;
    const int t      = lane & 3;
    const int row0   = blockIdx.x * BM;
    const int col0   = blockIdx.y * BN;

    // ldmatrix lane geometry
    const int mat   = lane >> 3;
    const int rowin = lane & 7;
    const int rowA  = warp_m * 64 + ((mat & 1) << 3) + rowin;   // + mt*16
    const int kA    = (mat >> 1) << 3;
    const int rowB0 = warp_n * 32 + ((mat >> 1) << 3) + rowin;  // + p*16
    const int kB    = (mat & 1) << 3;

    // fill geometry: 2 chunks of 16B per array per thread
    const int frow = tid >> 2;          // 0..63 (+64 for i=1)
    const int fseg = (tid & 3) * 16;    // byte offset within row

    float acc[4][4][4];
#pragma unroll
    for (int mt = 0; mt < 4; mt++)
#pragma unroll
        for (int nt = 0; nt < 4; nt++)
#pragma unroll
            for (int e = 0; e < 4; e++) acc[mt][nt][e] = 0.f;

    const int KT = K / BK;

    // ---- stage fill ----
    auto fill = [&](int kt, int s) {
        uint32_t sb = sbase + s * STAGEB;
        int kc = kt * BK + (fseg >> 1);   // element k offset of this 16B chunk
#pragma unroll
        for (int i = 0; i < 2; i++) {
            int r = frow + 64 * i;
            int gr = row0 + r;
            uint32_t ok = (gr < NROWS) ? 16u : 0u;
            size_t gi = (size_t)min(gr, NROWS - 1) * K + kc;
            uint32_t d = sb + r * ROWB + fseg;
            CP_ASYNC16(d + OFF_AHI, (const char*)&Ahi[gi], ok);
            CP_ASYNC16(d + OFF_ALO, (const char*)&Alo[gi], ok);
            size_t bi = (size_t)(col0 + r) * K + kc;
            CP_ASYNC16(d + OFF_BHI, (const char*)&Bhi[bi], 16u);
            CP_ASYNC16(d + OFF_BLO, (const char*)&Blo[bi], 16u);
        }
    };

    fill(0, 0);
    CP_COMMIT();

    for (int kt = 0; kt < KT; kt++) {
        int cur = kt & 1;
        if (kt + 1 < KT) {
            fill(kt + 1, cur ^ 1);
            CP_COMMIT();
            CP_WAIT(1);
        } else {
            CP_WAIT(0);
        }
        __syncthreads();

        uint32_t sb = sbase + cur * STAGEB;
#pragma unroll
        for (int ks = 0; ks < BK; ks += 16) {
            uint32_t bh[4][2], bl[4][2];
#pragma unroll
            for (int p = 0; p < 2; p++) {
                uint32_t ab_ = sb + (rowB0 + p * 16) * ROWB + (ks + kB) * 2;
                LDSM_X4(bh[2 * p][0], bh[2 * p][1], bh[2 * p + 1][0], bh[2 * p + 1][1],
                        ab_ + OFF_BHI);
                LDSM_X4(bl[2 * p][0], bl[2 * p][1], bl[2 * p + 1][0], bl[2 * p + 1][1],
                        ab_ + OFF_BLO);
            }
#pragma unroll
            for (int mt = 0; mt < 4; mt++) {
                uint32_t aa = sb + (rowA + mt * 16) * ROWB + (ks + kA) * 2;
                uint32_t ah[4], al[4];
                LDSM_X4(ah[0], ah[1], ah[2], ah[3], aa + OFF_AHI);
                LDSM_X4(al[0], al[1], al[2], al[3], aa + OFF_ALO);
#pragma unroll
                for (int nt = 0; nt < 4; nt++) {
                    mma_bf16(acc[mt][nt], ah, bh[nt]);
                    mma_bf16(acc[mt][nt], ah, bl[nt]);
                    mma_bf16(acc[mt][nt], al, bh[nt]);
                }
            }
        }
        __syncthreads();
    }

    // ---- epilogue ----
#pragma unroll
    for (int mt = 0; mt < 4; mt++) {
        int r0 = row0 + warp_m * 64 + mt * 16 + g;
        int r1 = r0 + 8;
#pragma unroll
        for (int nt = 0; nt < 4; nt++) {
            int c = col0 + warp_n * 32 + nt * 8 + 2 * t;
            float v0 = acc[mt][nt][0], v1 = acc[mt][nt][1];
            float v2 = acc[mt][nt][2], v3 = acc[mt][nt][3];
            if (mode == 0) {
                float b0 = __ldg(&bias[c]), b1 = __ldg(&bias[c + 1]);
                v0 = fmaxf(v0 + b0, 0.f); v1 = fmaxf(v1 + b1, 0.f);
                v2 = fmaxf(v2 + b0, 0.f); v3 = fmaxf(v3 + b1, 0.f);
                uint32_t h, l;
                if (r0 < NROWS) {
                    *(float2*)&Cf[(size_t)r0 * DH + c] = make_float2(v0, v1);
                    split2(v0, v1, h, l);
                    *(uint32_t*)&Chi[(size_t)r0 * DH + c] = h;
                    *(uint32_t*)&Clo[(size_t)r0 * DH + c] = l;
                }
                if (r1 < NROWS) {
                    *(float2*)&Cf[(size_t)r1 * DH + c] = make_float2(v2, v3);
                    split2(v2, v3, h, l);
                    *(uint32_t*)&Chi[(size_t)r1 * DH + c] = h;
                    *(uint32_t*)&Clo[(size_t)r1 * DH + c] = l;
                }
            } else {
                if (r0 < NROWS) *(float2*)&Cf[(size_t)r0 * DH + c] = make_float2(v0, v1);
                if (r1 < NROWS) *(float2*)&Cf[(size_t)r1 * DH + c] = make_float2(v2, v3);
            }
        }
    }
}

// ---------------------------------------------------------------------------
// A_raw[n] = sum_j cW[j]*tanh(z[n,j]+ab[j])*sigmoid(z[n,j+256]+bb[j]) + cb
// ---------------------------------------------------------------------------
__global__ __launch_bounds__(256) void araw_kernel(
    const float* __restrict__ ab, const float* __restrict__ bb,
    const float* __restrict__ cW, const float* __restrict__ cb,
    float* __restrict__ Araw)
{
    int row  = (blockIdx.x * blockDim.x + threadIdx.x) >> 5;
    int lane = threadIdx.x & 31;
    if (row >= NROWS) return;
    const float* zr = &g_z[(size_t)row * DH];
    float s = 0.f;
#pragma unroll
    for (int j = lane; j < DA; j += 32) {
        float za = zr[j]      + ab[j];
        float zb = zr[j + DA] + bb[j];
        float av = tanhf(za);
        float bv = 1.f / (1.f + expf(-zb));
        s += cW[j] * av * bv;
    }
#pragma unroll
    for (int m = 16; m > 0; m >>= 1) s += __shfl_xor_sync(0xffffffffu, s, m);
    if (lane == 0) Araw[row] = s + cb[0];
}

// ---------------------------------------------------------------------------
// instance_scores = hh @ cls_W^T + cls_b
// ---------------------------------------------------------------------------
__global__ __launch_bounds__(256) void cls_kernel(
    const float* __restrict__ clsW, const float* __restrict__ clsb,
    float* __restrict__ IS)
{
    int gw   = (blockIdx.x * blockDim.x + threadIdx.x) >> 5;
    int lane = threadIdx.x & 31;
    if (gw >= NROWS) return;
    const float* hr = &g_hh[(size_t)gw * DH];
    float c0 = 0.f, c1 = 0.f;
    for (int k = lane * 4; k < DH; k += 128) {
        float4 h  = *(const float4*)&hr[k];
        float4 w0 = *(const float4*)&clsW[k];
        float4 w1 = *(const float4*)&clsW[DH + k];
        c0 += h.x * w0.x + h.y * w0.y + h.z * w0.z + h.w * w0.w;
        c1 += h.x * w1.x + h.y * w1.y + h.z * w1.z + h.w * w1.w;
    }
#pragma unroll
    for (int m = 16; m > 0; m >>= 1) {
        c0 += __shfl_xor_sync(0xffffffffu, c0, m);
        c1 += __shfl_xor_sync(0xffffffffu, c1, m);
    }
    if (lane == 0) {
        IS[(size_t)gw * 2 + 0] = c0 + clsb[0];
        IS[(size_t)gw * 2 + 1] = c1 + clsb[1];
    }
}

// ---------------------------------------------------------------------------
// softmax-weighted pooled preds (single block, deterministic)
// ---------------------------------------------------------------------------
__global__ __launch_bounds__(1024) void preds_kernel(
    const float* __restrict__ Araw, const float* __restrict__ IS,
    float* __restrict__ preds)
{
    __shared__ float r0[1024];
    __shared__ float r1[1024];
    __shared__ float r2[1024];
    int tid = threadIdx.x;

    float m = -INFINITY;
    for (int n = tid; n < NROWS; n += 1024) m = fmaxf(m, Araw[n]);
    r0[tid] = m;
    __syncthreads();
    for (int s = 512; s > 0; s >>= 1) {
        if (tid < s) r0[tid] = fmaxf(r0[tid], r0[tid + s]);
        __syncthreads();
    }
    m = r0[0];
    __syncthreads();

    float s0 = 0.f, p0 = 0.f, p1 = 0.f;
    for (int n = tid; n < NROWS; n += 1024) {
        float e = expf(Araw[n] - m);
        s0 += e;
        p0 += e * IS[(size_t)n * 2 + 0];
        p1 += e * IS[(size_t)n * 2 + 1];
    }
    r0[tid] = s0; r1[tid] = p0; r2[tid] = p1;
    __syncthreads();
    for (int s = 512; s > 0; s >>= 1) {
        if (tid < s) {
            r0[tid] += r0[tid + s];
            r1[tid] += r1[tid + s];
            r2[tid] += r2[tid + s];
        }
        __syncthreads();
    }
    if (tid == 0) {
        preds[0] = r1[0] / r0[0];
        preds[1] = r2[0] / r0[0];
    }
}

// ---------------------------------------------------------------------------
// top-8 / bottom-8, single data pass + pool extraction (ties -> lower index)
// ---------------------------------------------------------------------------
__global__ __launch_bounds__(512) void topk_kernel(const float* __restrict__ Araw)
{
    __shared__ float pv[512 * 8];
    __shared__ int   pi[512 * 8];
    __shared__ float sv[512];
    __shared__ int   si[512];
    __shared__ int   sp[512];
    int tid = threadIdx.x;

    for (int pass = 0; pass < 2; pass++) {
        bool mx = (pass == 0);
        float tv[8];
        int   ti[8];
#pragma unroll
        for (int j = 0; j < 8; j++) { tv[j] = mx ? -INFINITY : INFINITY; ti[j] = 0x7fffffff; }
        for (int n = tid; n < NROWS; n += 512) {
            float v = Araw[n];
            bool better_last = mx ? (v > tv[7] || (v == tv[7] && n < ti[7]))
                                  : (v < tv[7] || (v == tv[7] && n < ti[7]));
            if (better_last) {
                int p = 7;
#pragma unroll
                for (int q = 7; q > 0; q--) {
                    bool up = mx ? (v > tv[q - 1] || (v == tv[q - 1] && n < ti[q - 1]))
                                 : (v < tv[q - 1] || (v == tv[q - 1] && n < ti[q - 1]));
                    if (up) { tv[q] = tv[q - 1]; ti[q] = ti[q - 1]; p = q - 1; }
                }
                tv[p] = v; ti[p] = n;
            }
        }
#pragma unroll
        for (int j = 0; j < 8; j++) { pv[tid * 8 + j] = tv[j]; pi[tid * 8 + j] = ti[j]; }
        __syncthreads();

        for (int it = 0; it < 8; it++) {
            float bk = mx ? -INFINITY : INFINITY;
            int bi = 0x7fffffff, bp = -1;
            for (int e = tid; e < 512 * 8; e += 512) {
                float v = pv[e];
                int   n = pi[e];
                bool better = mx ? (v > bk || (v == bk && n < bi))
                                 : (v < bk || (v == bk && n < bi));
                if (better) { bk = v; bi = n; bp = e; }
            }
            sv[tid] = bk; si[tid] = bi; sp[tid] = bp;
            __syncthreads();
            for (int s = 256; s > 0; s >>= 1) {
                if (tid < s) {
                    bool better = mx ? (sv[tid + s] > sv[tid] ||
                                        (sv[tid + s] == sv[tid] && si[tid + s] < si[tid]))
                                     : (sv[tid + s] < sv[tid] ||
                                        (sv[tid + s] == sv[tid] && si[tid + s] < si[tid]));
                    if (better) { sv[tid] = sv[tid + s]; si[tid] = si[tid + s]; sp[tid] = sp[tid + s]; }
                }
                __syncthreads();
            }
            if (tid == 0) {
                g_ids[pass * 8 + it] = si[0];
                pv[sp[0]] = mx ? -INFINITY : INFINITY;
                pi[sp[0]] = 0x7fffffff;
            }
            __syncthreads();
        }
        __syncthreads();
    }
}

// ---------------------------------------------------------------------------
// instance loss (16 selected rows, 1 warp each)
// ---------------------------------------------------------------------------
__global__ __launch_bounds__(512) void loss_kernel(
    const float* __restrict__ iW, const float* __restrict__ ib,
    float* __restrict__ loss)
{
    __shared__ float ls[16];
    int w    = threadIdx.x >> 5;
    int lane = threadIdx.x & 31;
    int id   = g_ids[w];
    const float* hr = &g_hh[(size_t)id * DH];
    float c0 = 0.f, c1 = 0.f;
    for (int k = lane * 4; k < DH; k += 128) {
        float4 h  = *(const float4*)&hr[k];
        float4 w0 = *(const float4*)&iW[k];
        float4 w1 = *(const float4*)&iW[DH + k];
        c0 += h.x * w0.x + h.y * w0.y + h.z * w0.z + h.w * w0.w;
        c1 += h.x * w1.x + h.y * w1.y + h.z * w1.z + h.w * w1.w;
    }
#pragma unroll
    for (int m = 16; m > 0; m >>= 1) {
        c0 += __shfl_xor_sync(0xffffffffu, c0, m);
        c1 += __shfl_xor_sync(0xffffffffu, c1, m);
    }
    if (lane == 0) {
        float l0 = c0 + ib[0], l1 = c1 + ib[1];
        float mm  = fmaxf(l0, l1);
        float lse = mm + logf(expf(l0 - mm) + expf(l1 - mm));
        float lt  = (w < KSEL) ? l1 : l0;
        ls[w] = lse - lt;
    }
    __syncthreads();
    if (threadIdx.x == 0) {
        float t = 0.f;
        for (int i = 0; i < 16; i++) t += ls[i];
        loss[0] = t / 16.f;
    }
}

// ---------------------------------------------------------------------------
extern "C" void kernel_launch(void* const* d_in, const int* in_sizes, int n_in,
                              void* d_out, int out_size)
{
    const float* h     = (const float*)d_in[0];
    const float* fcW   = (const float*)d_in[1];
    const float* fcb   = (const float*)d_in[2];
    const float* aW    = (const float*)d_in[3];
    const float* abv   = (const float*)d_in[4];
    const float* bW    = (const float*)d_in[5];
    const float* bbv   = (const float*)d_in[6];
    const float* cWv   = (const float*)d_in[7];
    const float* cbv   = (const float*)d_in[8];
    const float* clsW  = (const float*)d_in[9];
    const float* clsb  = (const float*)d_in[10];
    const float* instW = (const float*)d_in[11];
    const float* instb = (const float*)d_in[12];

    float* out   = (float*)d_out;
    float* preds = out;
    float* IS    = out + 2;
    float* Araw  = out + 2 + 2 * NROWS;
    float* loss  = out + 2 + 3 * NROWS;

    static int inited = 0;
    if (!inited) {
        cudaFuncSetAttribute(gemm_mma_kernel,
                             cudaFuncAttributeMaxDynamicSharedMemorySize, SMEM_GEMM);
        inited = 1;
    }

    __nv_bfloat16 *xhi, *xlo, *w1hi, *w1lo, *wabhi, *wablo, *hhhi, *hhlo;
    float *hhf, *zf;
    cudaGetSymbolAddress((void**)&xhi,   g_x_hi);
    cudaGetSymbolAddress((void**)&xlo,   g_x_lo);
    cudaGetSymbolAddress((void**)&w1hi,  g_w1_hi);
    cudaGetSymbolAddress((void**)&w1lo,  g_w1_lo);
    cudaGetSymbolAddress((void**)&wabhi, g_wab_hi);
    cudaGetSymbolAddress((void**)&wablo, g_wab_lo);
    cudaGetSymbolAddress((void**)&hhhi,  g_hh_hi);
    cudaGetSymbolAddress((void**)&hhlo,  g_hh_lo);
    cudaGetSymbolAddress((void**)&hhf,   g_hh);
    cudaGetSymbolAddress((void**)&zf,    g_z);

    // pre-split conversions
    {
        int n4 = NROWS * DIN / 4;
        conv_split_kernel<<<(n4 + 255) / 256, 256>>>(h, xhi, xlo, n4);
        int w4 = DH * DIN / 4;
        conv_split_kernel<<<(w4 + 255) / 256, 256>>>(fcW, w1hi, w1lo, w4);
        conv_wab_kernel<<<(DH * DH / 4 + 255) / 256, 256>>>(aW, bW);
    }

    dim3 grid((NROWS + BM - 1) / BM, DH / BN);   // (391, 4)

    // gemm1: hh = relu(X @ fcW^T + fcb)  (+ bf16 split of hh)
    gemm_mma_kernel<<<grid, 256, SMEM_GEMM>>>(xhi, xlo, w1hi, w1lo, fcb, DIN, 0,
                                              hhf, hhhi, hhlo);

    // gemm2: z = hh @ [Wa;Wb]^T
    gemm_mma_kernel<<<grid, 256, SMEM_GEMM>>>(hhhi, hhlo, wabhi, wablo, fcb, DH, 1,
                                              zf, (__nv_bfloat16*)0, (__nv_bfloat16*)0);

    araw_kernel<<<(NROWS * 32 + 255) / 256, 256>>>(abv, bbv, cWv, cbv, Araw);

    cls_kernel<<<(NROWS * 32 + 255) / 256, 256>>>(clsW, clsb, IS);

    preds_kernel<<<1, 1024>>>(Araw, IS, preds);

    topk_kernel<<<1, 512>>>(Araw);

    loss_kernel<<<1, 512>>>(instW, instb, loss);
}

// round 6
// speedup vs baseline: 2.7677x; 1.0480x over previous
#include <cuda_runtime.h>
#include <cuda_bf16.h>
#include <math.h>
#include <stdint.h>

#define NROWS 50000
#define DIN   1024
#define DH    512
#define DA    256
#define KSEL  8

#define BM 128
#define BN 128
#define BK 32

// smem per stage: Ahi, Alo (128 rows x 80B), Bhi, Blo
#define ROWB      80
#define OFF_AHI   0
#define OFF_ALO   10240
#define OFF_BHI   20480
#define OFF_BLO   30720
#define STAGEB    40960
#define SMEM_GEMM (2 * STAGEB)

// ---------------- scratch (static device allocations only) ----------------
__device__ __nv_bfloat16  g_x_hi[(size_t)NROWS * DIN];
__device__ __nv_bfloat16  g_x_lo[(size_t)NROWS * DIN];
__device__ __nv_bfloat16  g_hh_hi[(size_t)NROWS * DH];
__device__ __nv_bfloat16  g_hh_lo[(size_t)NROWS * DH];
__device__ __nv_bfloat16  g_w1_hi[(size_t)DH * DIN];
__device__ __nv_bfloat16  g_w1_lo[(size_t)DH * DIN];
__device__ __nv_bfloat16  g_wab_hi[(size_t)DH * DH];   // rows 0..255 Wa, 256..511 Wb
__device__ __nv_bfloat16  g_wab_lo[(size_t)DH * DH];
__device__ float          g_part[4][NROWS];            // per-colblock A_raw partials
__device__ int            g_ids[16];

// ============================ helpers ======================================
__device__ __forceinline__ uint32_t smem_u32(const void* p) {
    uint32_t a;
    asm("{ .reg .u64 t; cvta.to.shared.u64 t, %1; cvt.u32.u64 %0, t; }" : "=r"(a) : "l"(p));
    return a;
}
__device__ __forceinline__ void split2(float x, float y, uint32_t& hi, uint32_t& lo)
{
    __nv_bfloat16 hx = __float2bfloat16(x);
    __nv_bfloat16 hy = __float2bfloat16(y);
    __nv_bfloat16 lx = __float2bfloat16(x - __bfloat162float(hx));
    __nv_bfloat16 ly = __float2bfloat16(y - __bfloat162float(hy));
    hi = (uint32_t)__bfloat16_as_ushort(hx) | ((uint32_t)__bfloat16_as_ushort(hy) << 16);
    lo = (uint32_t)__bfloat16_as_ushort(lx) | ((uint32_t)__bfloat16_as_ushort(ly) << 16);
}
__device__ __forceinline__ void mma_bf16(float* d, const uint32_t* a, const uint32_t* b)
{
    asm volatile(
        "mma.sync.aligned.m16n8k16.row.col.f32.bf16.bf16.f32 "
        "{%0,%1,%2,%3}, {%4,%5,%6,%7}, {%8,%9}, {%0,%1,%2,%3};"
        : "+f"(d[0]), "+f"(d[1]), "+f"(d[2]), "+f"(d[3])
        : "r"(a[0]), "r"(a[1]), "r"(a[2]), "r"(a[3]), "r"(b[0]), "r"(b[1]));
}
#define LDSM_X4(r0, r1, r2, r3, addr) \
    asm volatile("ldmatrix.sync.aligned.m8n8.x4.shared.b16 {%0,%1,%2,%3}, [%4];" \
                 : "=r"(r0), "=r"(r1), "=r"(r2), "=r"(r3) : "r"(addr))
#define CP_ASYNC16(dst, src, sz) \
    asm volatile("cp.async.cg.shared.global [%0], [%1], 16, %2;" \
                 :: "r"(dst), "l"(src), "r"(sz))
#define CP_COMMIT()  asm volatile("cp.async.commit_group;" ::: "memory")
#define CP_WAIT(n)   asm volatile("cp.async.wait_group %0;" :: "n"(n) : "memory")

__device__ __forceinline__ float fast_sigmoid(float x) {
    return __fdividef(1.f, 1.f + __expf(-x));
}
__device__ __forceinline__ float fast_tanh(float x) {
    return __fdividef(2.f, 1.f + __expf(-2.f * x)) - 1.f;
}

// ============================ convert kernels ==============================
__global__ __launch_bounds__(256) void conv_split_kernel(
    const float* __restrict__ src, __nv_bfloat16* __restrict__ hi,
    __nv_bfloat16* __restrict__ lo, int n4)
{
    int i = blockIdx.x * blockDim.x + threadIdx.x;
    if (i >= n4) return;
    float4 v = ((const float4*)src)[i];
    uint32_t h0, l0, h1, l1;
    split2(v.x, v.y, h0, l0);
    split2(v.z, v.w, h1, l1);
    ((uint2*)hi)[i] = make_uint2(h0, h1);
    ((uint2*)lo)[i] = make_uint2(l0, l1);
}

__global__ __launch_bounds__(256) void conv_wab_kernel(
    const float* __restrict__ Wa, const float* __restrict__ Wb)
{
    int i = blockIdx.x * blockDim.x + threadIdx.x;
    if (i >= DH * DH / 4) return;
    int elem = i * 4;
    int row = elem / DH;
    int col = elem % DH;
    const float* src = (row < DA) ? &Wa[(size_t)row * DH + col]
                                  : &Wb[(size_t)(row - DA) * DH + col];
    float4 v = *(const float4*)src;
    uint32_t h0, l0, h1, l1;
    split2(v.x, v.y, h0, l0);
    split2(v.z, v.w, h1, l1);
    ((uint2*)g_wab_hi)[i] = make_uint2(h0, h1);
    ((uint2*)g_wab_lo)[i] = make_uint2(l0, l1);
}

// ===========================================================================
// 3xBF16 split GEMM (mma.sync + ldmatrix + cp.async double buffer)
//  mode 0 (gemm1): C = relu(A@B^T + bias) -> g_hh_hi/g_hh_lo (bf16 split only)
//  mode 1 (gemm2 fused): B tile interleaves Wa/Wb pairs; epilogue computes
//    partial A_raw[row] = sum_j c[j]*tanh(za+ab)*sigmoid(zb+bb) -> g_part[by]
// ===========================================================================
__global__ __launch_bounds__(256, 2) void gemm_mma_kernel(
    const __nv_bfloat16* __restrict__ Ahi, const __nv_bfloat16* __restrict__ Alo,
    const __nv_bfloat16* __restrict__ Bhi, const __nv_bfloat16* __restrict__ Blo,
    const float* __restrict__ bias,
    const float* __restrict__ abv, const float* __restrict__ bbv,
    const float* __restrict__ cWv,
    int K, int mode)
{
    extern __shared__ char smem[];
    const uint32_t sbase = smem_u32(smem);

    const int tid    = threadIdx.x;
    const int wid    = tid >> 5;
    const int lane   = tid & 31;
    const int warp_m = wid & 1;
    const int warp_n = wid >> 1;
    const int g      = lane >> 2;
    const int t      = lane & 3;
    const int row0   = blockIdx.x * BM;
    const int col0   = (mode == 0) ? blockIdx.y * BN : blockIdx.y * 64;

    const int mat   = lane >> 3;
    const int rowin = lane & 7;
    const int rowA  = warp_m * 64 + ((mat & 1) << 3) + rowin;
    const int kA    = (mat >> 1) << 3;
    const int rowB0 = warp_n * 32 + ((mat >> 1) << 3) + rowin;
    const int kB    = (mat & 1) << 3;

    const int frow = tid >> 2;
    const int fseg = (tid & 3) * 16;

    float acc[4][4][4];
#pragma unroll
    for (int mt = 0; mt < 4; mt++)
#pragma unroll
        for (int nt = 0; nt < 4; nt++)
#pragma unroll
            for (int e = 0; e < 4; e++) acc[mt][nt][e] = 0.f;

    const int KT = K / BK;

    auto fill = [&](int kt, int s) {
        uint32_t sb = sbase + s * STAGEB;
        int kc = kt * BK + (fseg >> 1);
#pragma unroll
        for (int i = 0; i < 2; i++) {
            int r = frow + 64 * i;
            int gr = row0 + r;
            uint32_t ok = (gr < NROWS) ? 16u : 0u;
            size_t gi = (size_t)min(gr, NROWS - 1) * K + kc;
            uint32_t d = sb + r * ROWB + fseg;
            CP_ASYNC16(d + OFF_AHI, (const char*)&Ahi[gi], ok);
            CP_ASYNC16(d + OFF_ALO, (const char*)&Alo[gi], ok);
            int brow;
            if (mode == 0) {
                brow = col0 + r;
            } else {
                int w = r >> 5, ii = r & 31;
                int j = col0 + (w << 4) + (ii & 15);
                brow = (ii < 16) ? j : j + DA;
            }
            size_t bi = (size_t)brow * K + kc;
            CP_ASYNC16(d + OFF_BHI, (const char*)&Bhi[bi], 16u);
            CP_ASYNC16(d + OFF_BLO, (const char*)&Blo[bi], 16u);
        }
    };

    fill(0, 0);
    CP_COMMIT();

    for (int kt = 0; kt < KT; kt++) {
        int cur = kt & 1;
        if (kt + 1 < KT) {
            fill(kt + 1, cur ^ 1);
            CP_COMMIT();
            CP_WAIT(1);
        } else {
            CP_WAIT(0);
        }
        __syncthreads();

        uint32_t sb = sbase + cur * STAGEB;
#pragma unroll
        for (int ks = 0; ks < BK; ks += 16) {
            uint32_t bh[4][2], bl[4][2];
#pragma unroll
            for (int p = 0; p < 2; p++) {
                uint32_t ab_ = sb + (rowB0 + p * 16) * ROWB + (ks + kB) * 2;
                LDSM_X4(bh[2 * p][0], bh[2 * p][1], bh[2 * p + 1][0], bh[2 * p + 1][1],
                        ab_ + OFF_BHI);
                LDSM_X4(bl[2 * p][0], bl[2 * p][1], bl[2 * p + 1][0], bl[2 * p + 1][1],
                        ab_ + OFF_BLO);
            }
#pragma unroll
            for (int mt = 0; mt < 4; mt++) {
                uint32_t aa = sb + (rowA + mt * 16) * ROWB + (ks + kA) * 2;
                uint32_t ah[4], al[4];
                LDSM_X4(ah[0], ah[1], ah[2], ah[3], aa + OFF_AHI);
                LDSM_X4(al[0], al[1], al[2], al[3], aa + OFF_ALO);
#pragma unroll
                for (int nt = 0; nt < 4; nt++) {
                    mma_bf16(acc[mt][nt], ah, bh[nt]);
                    mma_bf16(acc[mt][nt], ah, bl[nt]);
                    mma_bf16(acc[mt][nt], al, bh[nt]);
                }
            }
        }
        __syncthreads();
    }

    if (mode == 0) {
        // ---- gemm1 epilogue: relu(C+bias) -> bf16 hi/lo split ----
#pragma unroll
        for (int mt = 0; mt < 4; mt++) {
            int r0 = row0 + warp_m * 64 + mt * 16 + g;
            int r1 = r0 + 8;
#pragma unroll
            for (int nt = 0; nt < 4; nt++) {
                int c = col0 + warp_n * 32 + nt * 8 + 2 * t;
                float b0 = __ldg(&bias[c]), b1 = __ldg(&bias[c + 1]);
                float v0 = fmaxf(acc[mt][nt][0] + b0, 0.f);
                float v1 = fmaxf(acc[mt][nt][1] + b1, 0.f);
                float v2 = fmaxf(acc[mt][nt][2] + b0, 0.f);
                float v3 = fmaxf(acc[mt][nt][3] + b1, 0.f);
                uint32_t h, l;
                if (r0 < NROWS) {
                    split2(v0, v1, h, l);
                    *(uint32_t*)&g_hh_hi[(size_t)r0 * DH + c] = h;
                    *(uint32_t*)&g_hh_lo[(size_t)r0 * DH + c] = l;
                }
                if (r1 < NROWS) {
                    split2(v2, v3, h, l);
                    *(uint32_t*)&g_hh_hi[(size_t)r1 * DH + c] = h;
                    *(uint32_t*)&g_hh_lo[(size_t)r1 * DH + c] = l;
                }
            }
        }
    } else {
        // ---- gemm2 fused epilogue: partial A_raw reduction ----
        float* spart = (float*)smem;   // [128][4]
#pragma unroll
        for (int mt = 0; mt < 4; mt++) {
            float s0 = 0.f, s1 = 0.f;
#pragma unroll
            for (int nt = 0; nt < 2; nt++) {
                int j = col0 + warp_n * 16 + nt * 8 + 2 * t;
                float ab0 = __ldg(&abv[j]),     ab1 = __ldg(&abv[j + 1]);
                float bb0 = __ldg(&bbv[j]),     bb1 = __ldg(&bbv[j + 1]);
                float c0  = __ldg(&cWv[j]),     c1  = __ldg(&cWv[j + 1]);
                s0 += c0 * fast_tanh(acc[mt][nt][0] + ab0) * fast_sigmoid(acc[mt][nt + 2][0] + bb0);
                s0 += c1 * fast_tanh(acc[mt][nt][1] + ab1) * fast_sigmoid(acc[mt][nt + 2][1] + bb1);
                s1 += c0 * fast_tanh(acc[mt][nt][2] + ab0) * fast_sigmoid(acc[mt][nt + 2][2] + bb0);
                s1 += c1 * fast_tanh(acc[mt][nt][3] + ab1) * fast_sigmoid(acc[mt][nt + 2][3] + bb1);
            }
            // reduce over quad (t = 0..3)
            s0 += __shfl_xor_sync(0xffffffffu, s0, 1);
            s0 += __shfl_xor_sync(0xffffffffu, s0, 2);
            s1 += __shfl_xor_sync(0xffffffffu, s1, 1);
            s1 += __shfl_xor_sync(0xffffffffu, s1, 2);
            if (t == 0) {
                int rl = warp_m * 64 + mt * 16 + g;
                spart[rl * 4 + warp_n] = s0;
                spart[(rl + 8) * 4 + warp_n] = s1;
            }
        }
        __syncthreads();
        if (tid < 128) {
            int grow = row0 + tid;
            if (grow < NROWS) {
                float s = spart[tid * 4 + 0] + spart[tid * 4 + 1] +
                          spart[tid * 4 + 2] + spart[tid * 4 + 3];
                g_part[blockIdx.y][grow] = s;
            }
        }
    }
}

// ---------------------------------------------------------------------------
// A_raw final sum
// ---------------------------------------------------------------------------
__global__ __launch_bounds__(256) void araw_sum_kernel(
    const float* __restrict__ cb, float* __restrict__ Araw)
{
    int n = blockIdx.x * blockDim.x + threadIdx.x;
    if (n >= NROWS) return;
    Araw[n] = cb[0] + g_part[0][n] + g_part[1][n] + g_part[2][n] + g_part[3][n];
}

// ---------------------------------------------------------------------------
// instance_scores = hh @ cls_W^T + cls_b  (hh reconstructed from hi+lo)
// ---------------------------------------------------------------------------
__global__ __launch_bounds__(256) void cls_kernel(
    const float* __restrict__ clsW, const float* __restrict__ clsb,
    float* __restrict__ IS)
{
    int gw   = (blockIdx.x * blockDim.x + threadIdx.x) >> 5;
    int lane = threadIdx.x & 31;
    if (gw >= NROWS) return;
    const __nv_bfloat16* hhi = &g_hh_hi[(size_t)gw * DH];
    const __nv_bfloat16* hlo = &g_hh_lo[(size_t)gw * DH];
    float c0 = 0.f, c1 = 0.f;
    for (int k = lane * 4; k < DH; k += 128) {
        uint2 ph = *(const uint2*)&hhi[k];
        uint2 pl = *(const uint2*)&hlo[k];
        float h0 = __bfloat162float(__ushort_as_bfloat16((unsigned short)(ph.x & 0xffff)))
                 + __bfloat162float(__ushort_as_bfloat16((unsigned short)(pl.x & 0xffff)));
        float h1 = __bfloat162float(__ushort_as_bfloat16((unsigned short)(ph.x >> 16)))
                 + __bfloat162float(__ushort_as_bfloat16((unsigned short)(pl.x >> 16)));
        float h2 = __bfloat162float(__ushort_as_bfloat16((unsigned short)(ph.y & 0xffff)))
                 + __bfloat162float(__ushort_as_bfloat16((unsigned short)(pl.y & 0xffff)));
        float h3 = __bfloat162float(__ushort_as_bfloat16((unsigned short)(ph.y >> 16)))
                 + __bfloat162float(__ushort_as_bfloat16((unsigned short)(pl.y >> 16)));
        float4 w0 = *(const float4*)&clsW[k];
        float4 w1 = *(const float4*)&clsW[DH + k];
        c0 += h0 * w0.x + h1 * w0.y + h2 * w0.z + h3 * w0.w;
        c1 += h0 * w1.x + h1 * w1.y + h2 * w1.z + h3 * w1.w;
    }
#pragma unroll
    for (int m = 16; m > 0; m >>= 1) {
        c0 += __shfl_xor_sync(0xffffffffu, c0, m);
        c1 += __shfl_xor_sync(0xffffffffu, c1, m);
    }
    if (lane == 0) {
        IS[(size_t)gw * 2 + 0] = c0 + clsb[0];
        IS[(size_t)gw * 2 + 1] = c1 + clsb[1];
    }
}

// ---------------------------------------------------------------------------
// softmax-weighted pooled preds (single block, deterministic)
// ---------------------------------------------------------------------------
__global__ __launch_bounds__(1024) void preds_kernel(
    const float* __restrict__ Araw, const float* __restrict__ IS,
    float* __restrict__ preds)
{
    __shared__ float r0[1024];
    __shared__ float r1[1024];
    __shared__ float r2[1024];
    int tid = threadIdx.x;

    float m = -INFINITY;
    for (int n = tid; n < NROWS; n += 1024) m = fmaxf(m, Araw[n]);
    r0[tid] = m;
    __syncthreads();
    for (int s = 512; s > 0; s >>= 1) {
        if (tid < s) r0[tid] = fmaxf(r0[tid], r0[tid + s]);
        __syncthreads();
    }
    m = r0[0];
    __syncthreads();

    float s0 = 0.f, p0 = 0.f, p1 = 0.f;
    for (int n = tid; n < NROWS; n += 1024) {
        float e = expf(Araw[n] - m);
        s0 += e;
        p0 += e * IS[(size_t)n * 2 + 0];
        p1 += e * IS[(size_t)n * 2 + 1];
    }
    r0[tid] = s0; r1[tid] = p0; r2[tid] = p1;
    __syncthreads();
    for (int s = 512; s > 0; s >>= 1) {
        if (tid < s) {
            r0[tid] += r0[tid + s];
            r1[tid] += r1[tid + s];
            r2[tid] += r2[tid + s];
        }
        __syncthreads();
    }
    if (tid == 0) {
        preds[0] = r1[0] / r0[0];
        preds[1] = r2[0] / r0[0];
    }
}

// ---------------------------------------------------------------------------
// top-8 / bottom-8, single data pass + pool extraction (ties -> lower index)
// ---------------------------------------------------------------------------
__global__ __launch_bounds__(512) void topk_kernel(const float* __restrict__ Araw)
{
    __shared__ float pv[512 * 8];
    __shared__ int   pi[512 * 8];
    __shared__ float sv[512];
    __shared__ int   si[512];
    __shared__ int   sp[512];
    int tid = threadIdx.x;

    for (int pass = 0; pass < 2; pass++) {
        bool mx = (pass == 0);
        float tv[8];
        int   ti[8];
#pragma unroll
        for (int j = 0; j < 8; j++) { tv[j] = mx ? -INFINITY : INFINITY; ti[j] = 0x7fffffff; }
        for (int n = tid; n < NROWS; n += 512) {
            float v = Araw[n];
            bool better_last = mx ? (v > tv[7] || (v == tv[7] && n < ti[7]))
                                  : (v < tv[7] || (v == tv[7] && n < ti[7]));
            if (better_last) {
                int p = 7;
#pragma unroll
                for (int q = 7; q > 0; q--) {
                    bool up = mx ? (v > tv[q - 1] || (v == tv[q - 1] && n < ti[q - 1]))
                                 : (v < tv[q - 1] || (v == tv[q - 1] && n < ti[q - 1]));
                    if (up) { tv[q] = tv[q - 1]; ti[q] = ti[q - 1]; p = q - 1; }
                }
                tv[p] = v; ti[p] = n;
            }
        }
#pragma unroll
        for (int j = 0; j < 8; j++) { pv[tid * 8 + j] = tv[j]; pi[tid * 8 + j] = ti[j]; }
        __syncthreads();

        for (int it = 0; it < 8; it++) {
            float bk = mx ? -INFINITY : INFINITY;
            int bi = 0x7fffffff, bp = -1;
            for (int e = tid; e < 512 * 8; e += 512) {
                float v = pv[e];
                int   n = pi[e];
                bool better = mx ? (v > bk || (v == bk && n < bi))
                                 : (v < bk || (v == bk && n < bi));
                if (better) { bk = v; bi = n; bp = e; }
            }
            sv[tid] = bk; si[tid] = bi; sp[tid] = bp;
            __syncthreads();
            for (int s = 256; s > 0; s >>= 1) {
                if (tid < s) {
                    bool better = mx ? (sv[tid + s] > sv[tid] ||
                                        (sv[tid + s] == sv[tid] && si[tid + s] < si[tid]))
                                     : (sv[tid + s] < sv[tid] ||
                                        (sv[tid + s] == sv[tid] && si[tid + s] < si[tid]));
                    if (better) { sv[tid] = sv[tid + s]; si[tid] = si[tid + s]; sp[tid] = sp[tid + s]; }
                }
                __syncthreads();
            }
            if (tid == 0) {
                g_ids[pass * 8 + it] = si[0];
                pv[sp[0]] = mx ? -INFINITY : INFINITY;
                pi[sp[0]] = 0x7fffffff;
            }
            __syncthreads();
        }
        __syncthreads();
    }
}

// ---------------------------------------------------------------------------
// instance loss (16 selected rows, 1 warp each; hh from hi+lo)
// ---------------------------------------------------------------------------
__global__ __launch_bounds__(512) void loss_kernel(
    const float* __restrict__ iW, const float* __restrict__ ib,
    float* __restrict__ loss)
{
    __shared__ float ls[16];
    int w    = threadIdx.x >> 5;
    int lane = threadIdx.x & 31;
    int id   = g_ids[w];
    const __nv_bfloat16* hhi = &g_hh_hi[(size_t)id * DH];
    const __nv_bfloat16* hlo = &g_hh_lo[(size_t)id * DH];
    float c0 = 0.f, c1 = 0.f;
    for (int k = lane * 4; k < DH; k += 128) {
        uint2 ph = *(const uint2*)&hhi[k];
        uint2 pl = *(const uint2*)&hlo[k];
        float h0 = __bfloat162float(__ushort_as_bfloat16((unsigned short)(ph.x & 0xffff)))
                 + __bfloat162float(__ushort_as_bfloat16((unsigned short)(pl.x & 0xffff)));
        float h1 = __bfloat162float(__ushort_as_bfloat16((unsigned short)(ph.x >> 16)))
                 + __bfloat162float(__ushort_as_bfloat16((unsigned short)(pl.x >> 16)));
        float h2 = __bfloat162float(__ushort_as_bfloat16((unsigned short)(ph.y & 0xffff)))
                 + __bfloat162float(__ushort_as_bfloat16((unsigned short)(pl.y & 0xffff)));
        float h3 = __bfloat162float(__ushort_as_bfloat16((unsigned short)(ph.y >> 16)))
                 + __bfloat162float(__ushort_as_bfloat16((unsigned short)(pl.y >> 16)));
        float4 w0 = *(const float4*)&iW[k];
        float4 w1 = *(const float4*)&iW[DH + k];
        c0 += h0 * w0.x + h1 * w0.y + h2 * w0.z + h3 * w0.w;
        c1 += h0 * w1.x + h1 * w1.y + h2 * w1.z + h3 * w1.w;
    }
#pragma unroll
    for (int m = 16; m > 0; m >>= 1) {
        c0 += __shfl_xor_sync(0xffffffffu, c0, m);
        c1 += __shfl_xor_sync(0xffffffffu, c1, m);
    }
    if (lane == 0) {
        float l0 = c0 + ib[0], l1 = c1 + ib[1];
        float mm  = fmaxf(l0, l1);
        float lse = mm + logf(expf(l0 - mm) + expf(l1 - mm));
        float lt  = (w < KSEL) ? l1 : l0;
        ls[w] = lse - lt;
    }
    __syncthreads();
    if (threadIdx.x == 0) {
        float t = 0.f;
        for (int i = 0; i < 16; i++) t += ls[i];
        loss[0] = t / 16.f;
    }
}

// ---------------------------------------------------------------------------
extern "C" void kernel_launch(void* const* d_in, const int* in_sizes, int n_in,
                              void* d_out, int out_size)
{
    const float* h     = (const float*)d_in[0];
    const float* fcW   = (const float*)d_in[1];
    const float* fcb   = (const float*)d_in[2];
    const float* aW    = (const float*)d_in[3];
    const float* abv   = (const float*)d_in[4];
    const float* bW    = (const float*)d_in[5];
    const float* bbv   = (const float*)d_in[6];
    const float* cWv   = (const float*)d_in[7];
    const float* cbv   = (const float*)d_in[8];
    const float* clsW  = (const float*)d_in[9];
    const float* clsb  = (const float*)d_in[10];
    const float* instW = (const float*)d_in[11];
    const float* instb = (const float*)d_in[12];

    float* out   = (float*)d_out;
    float* preds = out;
    float* IS    = out + 2;
    float* Araw  = out + 2 + 2 * NROWS;
    float* loss  = out + 2 + 3 * NROWS;

    static int inited = 0;
    if (!inited) {
        cudaFuncSetAttribute(gemm_mma_kernel,
                             cudaFuncAttributeMaxDynamicSharedMemorySize, SMEM_GEMM);
        inited = 1;
    }

    __nv_bfloat16 *xhi, *xlo, *w1hi, *w1lo, *wabhi, *wablo, *hhhi, *hhlo;
    cudaGetSymbolAddress((void**)&xhi,   g_x_hi);
    cudaGetSymbolAddress((void**)&xlo,   g_x_lo);
    cudaGetSymbolAddress((void**)&w1hi,  g_w1_hi);
    cudaGetSymbolAddress((void**)&w1lo,  g_w1_lo);
    cudaGetSymbolAddress((void**)&wabhi, g_wab_hi);
    cudaGetSymbolAddress((void**)&wablo, g_wab_lo);
    cudaGetSymbolAddress((void**)&hhhi,  g_hh_hi);
    cudaGetSymbolAddress((void**)&hhlo,  g_hh_lo);

    // pre-split conversions
    {
        int n4 = NROWS * DIN / 4;
        conv_split_kernel<<<(n4 + 255) / 256, 256>>>(h, xhi, xlo, n4);
        int w4 = DH * DIN / 4;
        conv_split_kernel<<<(w4 + 255) / 256, 256>>>(fcW, w1hi, w1lo, w4);
        conv_wab_kernel<<<(DH * DH / 4 + 255) / 256, 256>>>(aW, bW);
    }

    dim3 grid((NROWS + BM - 1) / BM, 4);   // (391, 4)

    // gemm1: hh = relu(X @ fcW^T + fcb) -> hi/lo split
    gemm_mma_kernel<<<grid, 256, SMEM_GEMM>>>(xhi, xlo, w1hi, w1lo, fcb,
                                              (const float*)0, (const float*)0,
                                              (const float*)0, DIN, 0);

    // gemm2 fused: partial A_raw into g_part
    gemm_mma_kernel<<<grid, 256, SMEM_GEMM>>>(hhhi, hhlo, wabhi, wablo,
                                              (const float*)0, abv, bbv, cWv,
                                              DH, 1);

    araw_sum_kernel<<<(NROWS + 255) / 256, 256>>>(cbv, Araw);

    cls_kernel<<<(NROWS * 32 + 255) / 256, 256>>>(clsW, clsb, IS);

    preds_kernel<<<1, 1024>>>(Araw, IS, preds);

    topk_kernel<<<1, 512>>>(Araw);

    loss_kernel<<<1, 512>>>(instW, instb, loss);
}

// round 7
// speedup vs baseline: 2.7782x; 1.0038x over previous
#include <cuda_runtime.h>
#include <cuda_bf16.h>
#include <math.h>
#include <stdint.h>

#define NROWS 50000
#define DIN   1024
#define DH    512
#define DA    256
#define KSEL  8
#define NB_POST 196   // ceil(50000/256)

#define BM 128
#define BN 128
#define BK 32

#define ROWB      80
#define OFF_AHI   0
#define OFF_ALO   10240
#define OFF_BHI   20480
#define OFF_BLO   30720
#define STAGEB    40960
#define SMEM_GEMM (2 * STAGEB)

// ---------------- scratch (static device allocations only) ----------------
__device__ __nv_bfloat16  g_x_hi[(size_t)NROWS * DIN];
__device__ __nv_bfloat16  g_x_lo[(size_t)NROWS * DIN];
__device__ __nv_bfloat16  g_hh_hi[(size_t)NROWS * DH];
__device__ __nv_bfloat16  g_hh_lo[(size_t)NROWS * DH];
__device__ __nv_bfloat16  g_w1_hi[(size_t)DH * DIN];
__device__ __nv_bfloat16  g_w1_lo[(size_t)DH * DIN];
__device__ __nv_bfloat16  g_wab_hi[(size_t)DH * DH];   // rows 0..255 Wa, 256..511 Wb
__device__ __nv_bfloat16  g_wab_lo[(size_t)DH * DH];
__device__ float          g_part[4][NROWS];            // A_raw partials per col-block
__device__ float          g_cls_part[4][NROWS][2];     // cls partials per col-block
__device__ float          g_red[NB_POST][4];           // {max, sum e, sum e*is0, sum e*is1}
__device__ int            g_ids[16];

// ============================ helpers ======================================
__device__ __forceinline__ uint32_t smem_u32(const void* p) {
    uint32_t a;
    asm("{ .reg .u64 t; cvta.to.shared.u64 t, %1; cvt.u32.u64 %0, t; }" : "=r"(a) : "l"(p));
    return a;
}
__device__ __forceinline__ void split2(float x, float y, uint32_t& hi, uint32_t& lo)
{
    __nv_bfloat16 hx = __float2bfloat16(x);
    __nv_bfloat16 hy = __float2bfloat16(y);
    __nv_bfloat16 lx = __float2bfloat16(x - __bfloat162float(hx));
    __nv_bfloat16 ly = __float2bfloat16(y - __bfloat162float(hy));
    hi = (uint32_t)__bfloat16_as_ushort(hx) | ((uint32_t)__bfloat16_as_ushort(hy) << 16);
    lo = (uint32_t)__bfloat16_as_ushort(lx) | ((uint32_t)__bfloat16_as_ushort(ly) << 16);
}
__device__ __forceinline__ void mma_bf16(float* d, const uint32_t* a, const uint32_t* b)
{
    asm volatile(
        "mma.sync.aligned.m16n8k16.row.col.f32.bf16.bf16.f32 "
        "{%0,%1,%2,%3}, {%4,%5,%6,%7}, {%8,%9}, {%0,%1,%2,%3};"
        : "+f"(d[0]), "+f"(d[1]), "+f"(d[2]), "+f"(d[3])
        : "r"(a[0]), "r"(a[1]), "r"(a[2]), "r"(a[3]), "r"(b[0]), "r"(b[1]));
}
#define LDSM_X4(r0, r1, r2, r3, addr) \
    asm volatile("ldmatrix.sync.aligned.m8n8.x4.shared.b16 {%0,%1,%2,%3}, [%4];" \
                 : "=r"(r0), "=r"(r1), "=r"(r2), "=r"(r3) : "r"(addr))
#define CP_ASYNC16(dst, src, sz) \
    asm volatile("cp.async.cg.shared.global [%0], [%1], 16, %2;" \
                 :: "r"(dst), "l"(src), "r"(sz))
#define CP_COMMIT()  asm volatile("cp.async.commit_group;" ::: "memory")
#define CP_WAIT(n)   asm volatile("cp.async.wait_group %0;" :: "n"(n) : "memory")

__device__ __forceinline__ float fast_sigmoid(float x) {
    return __fdividef(1.f, 1.f + __expf(-x));
}
__device__ __forceinline__ float fast_tanh(float x) {
    return __fdividef(2.f, 1.f + __expf(-2.f * x)) - 1.f;
}

// ============================ convert kernels ==============================
__global__ __launch_bounds__(256) void conv_split_kernel(
    const float* __restrict__ src, __nv_bfloat16* __restrict__ hi,
    __nv_bfloat16* __restrict__ lo, int n4)
{
    int i = blockIdx.x * blockDim.x + threadIdx.x;
    if (i >= n4) return;
    float4 v = ((const float4*)src)[i];
    uint32_t h0, l0, h1, l1;
    split2(v.x, v.y, h0, l0);
    split2(v.z, v.w, h1, l1);
    ((uint2*)hi)[i] = make_uint2(h0, h1);
    ((uint2*)lo)[i] = make_uint2(l0, l1);
}

__global__ __launch_bounds__(256) void conv_wab_kernel(
    const float* __restrict__ Wa, const float* __restrict__ Wb)
{
    int i = blockIdx.x * blockDim.x + threadIdx.x;
    if (i >= DH * DH / 4) return;
    int elem = i * 4;
    int row = elem / DH;
    int col = elem % DH;
    const float* src = (row < DA) ? &Wa[(size_t)row * DH + col]
                                  : &Wb[(size_t)(row - DA) * DH + col];
    float4 v = *(const float4*)src;
    uint32_t h0, l0, h1, l1;
    split2(v.x, v.y, h0, l0);
    split2(v.z, v.w, h1, l1);
    ((uint2*)g_wab_hi)[i] = make_uint2(h0, h1);
    ((uint2*)g_wab_lo)[i] = make_uint2(l0, l1);
}

// ===========================================================================
// 3xBF16 split GEMM (mma.sync + ldmatrix + cp.async double buffer)
//  grid = (colBlocks, rowBlocks): consecutive CTAs share the A tile -> L2 reuse
//  mode 0 (gemm1): relu(A@B^T + bias) -> hh hi/lo split + cls partials
//  mode 1 (gemm2): fused A_raw partial reduction -> g_part
// ===========================================================================
__global__ __launch_bounds__(256, 2) void gemm_mma_kernel(
    const __nv_bfloat16* __restrict__ Ahi, const __nv_bfloat16* __restrict__ Alo,
    const __nv_bfloat16* __restrict__ Bhi, const __nv_bfloat16* __restrict__ Blo,
    const float* __restrict__ bias,
    const float* __restrict__ abv, const float* __restrict__ bbv,
    const float* __restrict__ cWv, const float* __restrict__ clsW,
    int K, int mode)
{
    extern __shared__ char smem[];
    const uint32_t sbase = smem_u32(smem);

    const int tid    = threadIdx.x;
    const int wid    = tid >> 5;
    const int lane   = tid & 31;
    const int warp_m = wid & 1;
    const int warp_n = wid >> 1;
    const int g      = lane >> 2;
    const int t      = lane & 3;
    const int bx     = blockIdx.x;                  // column block (fastest)
    const int row0   = blockIdx.y * BM;
    const int col0   = (mode == 0) ? bx * BN : bx * 64;

    const int mat   = lane >> 3;
    const int rowin = lane & 7;
    const int rowA  = warp_m * 64 + ((mat & 1) << 3) + rowin;
    const int kA    = (mat >> 1) << 3;
    const int rowB0 = warp_n * 32 + ((mat >> 1) << 3) + rowin;
    const int kB    = (mat & 1) << 3;

    const int frow = tid >> 2;
    const int fseg = (tid & 3) * 16;

    float acc[4][4][4];
#pragma unroll
    for (int mt = 0; mt < 4; mt++)
#pragma unroll
        for (int nt = 0; nt < 4; nt++)
#pragma unroll
            for (int e = 0; e < 4; e++) acc[mt][nt][e] = 0.f;

    const int KT = K / BK;

    auto fill = [&](int kt, int s) {
        uint32_t sb = sbase + s * STAGEB;
        int kc = kt * BK + (fseg >> 1);
#pragma unroll
        for (int i = 0; i < 2; i++) {
            int r = frow + 64 * i;
            int gr = row0 + r;
            uint32_t ok = (gr < NROWS) ? 16u : 0u;
            size_t gi = (size_t)min(gr, NROWS - 1) * K + kc;
            uint32_t d = sb + r * ROWB + fseg;
            CP_ASYNC16(d + OFF_AHI, (const char*)&Ahi[gi], ok);
            CP_ASYNC16(d + OFF_ALO, (const char*)&Alo[gi], ok);
            int brow;
            if (mode == 0) {
                brow = col0 + r;
            } else {
                int w = r >> 5, ii = r & 31;
                int j = col0 + (w << 4) + (ii & 15);
                brow = (ii < 16) ? j : j + DA;
            }
            size_t bi = (size_t)brow * K + kc;
            CP_ASYNC16(d + OFF_BHI, (const char*)&Bhi[bi], 16u);
            CP_ASYNC16(d + OFF_BLO, (const char*)&Blo[bi], 16u);
        }
    };

    fill(0, 0);
    CP_COMMIT();

    for (int kt = 0; kt < KT; kt++) {
        int cur = kt & 1;
        if (kt + 1 < KT) {
            fill(kt + 1, cur ^ 1);
            CP_COMMIT();
            CP_WAIT(1);
        } else {
            CP_WAIT(0);
        }
        __syncthreads();

        uint32_t sb = sbase + cur * STAGEB;
#pragma unroll
        for (int ks = 0; ks < BK; ks += 16) {
            uint32_t bh[4][2], bl[4][2];
#pragma unroll
            for (int p = 0; p < 2; p++) {
                uint32_t ab_ = sb + (rowB0 + p * 16) * ROWB + (ks + kB) * 2;
                LDSM_X4(bh[2 * p][0], bh[2 * p][1], bh[2 * p + 1][0], bh[2 * p + 1][1],
                        ab_ + OFF_BHI);
                LDSM_X4(bl[2 * p][0], bl[2 * p][1], bl[2 * p + 1][0], bl[2 * p + 1][1],
                        ab_ + OFF_BLO);
            }
#pragma unroll
            for (int mt = 0; mt < 4; mt++) {
                uint32_t aa = sb + (rowA + mt * 16) * ROWB + (ks + kA) * 2;
                uint32_t ah[4], al[4];
                LDSM_X4(ah[0], ah[1], ah[2], ah[3], aa + OFF_AHI);
                LDSM_X4(al[0], al[1], al[2], al[3], aa + OFF_ALO);
#pragma unroll
                for (int nt = 0; nt < 4; nt++) {
                    mma_bf16(acc[mt][nt], ah, bh[nt]);
                    mma_bf16(acc[mt][nt], ah, bl[nt]);
                    mma_bf16(acc[mt][nt], al, bh[nt]);
                }
            }
        }
        __syncthreads();
    }

    if (mode == 0) {
        // ---- gemm1 epilogue: relu(C+bias) -> hh hi/lo split + cls partials ----
        float* sc0 = (float*)smem;           // [128][4]
        float* sc1 = (float*)smem + 512;     // [128][4]
#pragma unroll
        for (int mt = 0; mt < 4; mt++) {
            int r0 = row0 + warp_m * 64 + mt * 16 + g;
            int r1 = r0 + 8;
            float p00 = 0.f, p01 = 0.f, p10 = 0.f, p11 = 0.f;
#pragma unroll
            for (int nt = 0; nt < 4; nt++) {
                int c = col0 + warp_n * 32 + nt * 8 + 2 * t;
                float b0 = __ldg(&bias[c]), b1 = __ldg(&bias[c + 1]);
                float v0 = fmaxf(acc[mt][nt][0] + b0, 0.f);
                float v1 = fmaxf(acc[mt][nt][1] + b1, 0.f);
                float v2 = fmaxf(acc[mt][nt][2] + b0, 0.f);
                float v3 = fmaxf(acc[mt][nt][3] + b1, 0.f);
                float w00 = __ldg(&clsW[c]),      w01 = __ldg(&clsW[c + 1]);
                float w10 = __ldg(&clsW[DH + c]), w11 = __ldg(&clsW[DH + c + 1]);
                p00 += v0 * w00 + v1 * w01;
                p01 += v0 * w10 + v1 * w11;
                p10 += v2 * w00 + v3 * w01;
                p11 += v2 * w10 + v3 * w11;
                uint32_t hh, ll;
                if (r0 < NROWS) {
                    split2(v0, v1, hh, ll);
                    *(uint32_t*)&g_hh_hi[(size_t)r0 * DH + c] = hh;
                    *(uint32_t*)&g_hh_lo[(size_t)r0 * DH + c] = ll;
                }
                if (r1 < NROWS) {
                    split2(v2, v3, hh, ll);
                    *(uint32_t*)&g_hh_hi[(size_t)r1 * DH + c] = hh;
                    *(uint32_t*)&g_hh_lo[(size_t)r1 * DH + c] = ll;
                }
            }
            p00 += __shfl_xor_sync(0xffffffffu, p00, 1);
            p00 += __shfl_xor_sync(0xffffffffu, p00, 2);
            p01 += __shfl_xor_sync(0xffffffffu, p01, 1);
            p01 += __shfl_xor_sync(0xffffffffu, p01, 2);
            p10 += __shfl_xor_sync(0xffffffffu, p10, 1);
            p10 += __shfl_xor_sync(0xffffffffu, p10, 2);
            p11 += __shfl_xor_sync(0xffffffffu, p11, 1);
            p11 += __shfl_xor_sync(0xffffffffu, p11, 2);
            if (t == 0) {
                int rl = warp_m * 64 + mt * 16 + g;
                sc0[rl * 4 + warp_n] = p00;
                sc1[rl * 4 + warp_n] = p01;
                sc0[(rl + 8) * 4 + warp_n] = p10;
                sc1[(rl + 8) * 4 + warp_n] = p11;
            }
        }
        __syncthreads();
        if (tid < 128) {
            int grow = row0 + tid;
            if (grow < NROWS) {
                g_cls_part[bx][grow][0] = sc0[tid * 4 + 0] + sc0[tid * 4 + 1] +
                                          sc0[tid * 4 + 2] + sc0[tid * 4 + 3];
                g_cls_part[bx][grow][1] = sc1[tid * 4 + 0] + sc1[tid * 4 + 1] +
                                          sc1[tid * 4 + 2] + sc1[tid * 4 + 3];
            }
        }
    } else {
        // ---- gemm2 fused epilogue: partial A_raw reduction ----
        float* spart = (float*)smem;   // [128][4]
#pragma unroll
        for (int mt = 0; mt < 4; mt++) {
            float s0 = 0.f, s1 = 0.f;
#pragma unroll
            for (int nt = 0; nt < 2; nt++) {
                int j = col0 + warp_n * 16 + nt * 8 + 2 * t;
                float ab0 = __ldg(&abv[j]), ab1 = __ldg(&abv[j + 1]);
                float bb0 = __ldg(&bbv[j]), bb1 = __ldg(&bbv[j + 1]);
                float c0  = __ldg(&cWv[j]), c1  = __ldg(&cWv[j + 1]);
                s0 += c0 * fast_tanh(acc[mt][nt][0] + ab0) * fast_sigmoid(acc[mt][nt + 2][0] + bb0);
                s0 += c1 * fast_tanh(acc[mt][nt][1] + ab1) * fast_sigmoid(acc[mt][nt + 2][1] + bb1);
                s1 += c0 * fast_tanh(acc[mt][nt][2] + ab0) * fast_sigmoid(acc[mt][nt + 2][2] + bb0);
                s1 += c1 * fast_tanh(acc[mt][nt][3] + ab1) * fast_sigmoid(acc[mt][nt + 2][3] + bb1);
            }
            s0 += __shfl_xor_sync(0xffffffffu, s0, 1);
            s0 += __shfl_xor_sync(0xffffffffu, s0, 2);
            s1 += __shfl_xor_sync(0xffffffffu, s1, 1);
            s1 += __shfl_xor_sync(0xffffffffu, s1, 2);
            if (t == 0) {
                int rl = warp_m * 64 + mt * 16 + g;
                spart[rl * 4 + warp_n] = s0;
                spart[(rl + 8) * 4 + warp_n] = s1;
            }
        }
        __syncthreads();
        if (tid < 128) {
            int grow = row0 + tid;
            if (grow < NROWS) {
                g_part[bx][grow] = spart[tid * 4 + 0] + spart[tid * 4 + 1] +
                                   spart[tid * 4 + 2] + spart[tid * 4 + 3];
            }
        }
    }
}

// ---------------------------------------------------------------------------
// post1: Araw + IS finalize + per-block softmax partials (deterministic)
// ---------------------------------------------------------------------------
__global__ __launch_bounds__(256) void post1_kernel(
    const float* __restrict__ cb, const float* __restrict__ clsb,
    float* __restrict__ Araw, float* __restrict__ IS)
{
    __shared__ float rm[256], r0[256], r1[256], r2[256];
    int tid = threadIdx.x;
    int n   = blockIdx.x * 256 + tid;
    bool valid = (n < NROWS);

    float a = -INFINITY, is0 = 0.f, is1 = 0.f;
    if (valid) {
        a = cb[0] + g_part[0][n] + g_part[1][n] + g_part[2][n] + g_part[3][n];
        Araw[n] = a;
        is0 = clsb[0] + g_cls_part[0][n][0] + g_cls_part[1][n][0] +
                        g_cls_part[2][n][0] + g_cls_part[3][n][0];
        is1 = clsb[1] + g_cls_part[0][n][1] + g_cls_part[1][n][1] +
                        g_cls_part[2][n][1] + g_cls_part[3][n][1];
        IS[(size_t)n * 2 + 0] = is0;
        IS[(size_t)n * 2 + 1] = is1;
    }

    rm[tid] = a;
    __syncthreads();
    for (int s = 128; s > 0; s >>= 1) {
        if (tid < s) rm[tid] = fmaxf(rm[tid], rm[tid + s]);
        __syncthreads();
    }
    float m = rm[0];
    __syncthreads();

    float e = valid ? expf(a - m) : 0.f;
    r0[tid] = e; r1[tid] = e * is0; r2[tid] = e * is1;
    __syncthreads();
    for (int s = 128; s > 0; s >>= 1) {
        if (tid < s) {
            r0[tid] += r0[tid + s];
            r1[tid] += r1[tid + s];
            r2[tid] += r2[tid + s];
        }
        __syncthreads();
    }
    if (tid == 0) {
        g_red[blockIdx.x][0] = m;
        g_red[blockIdx.x][1] = r0[0];
        g_red[blockIdx.x][2] = r1[0];
        g_red[blockIdx.x][3] = r2[0];
    }
}

// ---------------------------------------------------------------------------
// finalize: combine block partials -> preds
// ---------------------------------------------------------------------------
__global__ __launch_bounds__(256) void finalize_kernel(float* __restrict__ preds)
{
    __shared__ float rm[256], r0[256], r1[256], r2[256];
    int tid = threadIdx.x;
    float m = (tid < NB_POST) ? g_red[tid][0] : -INFINITY;
    rm[tid] = m;
    __syncthreads();
    for (int s = 128; s > 0; s >>= 1) {
        if (tid < s) rm[tid] = fmaxf(rm[tid], rm[tid + s]);
        __syncthreads();
    }
    float M = rm[0];
    __syncthreads();
    float se = 0.f, s0 = 0.f, s1 = 0.f;
    if (tid < NB_POST) {
        float w = expf(g_red[tid][0] - M);
        se = w * g_red[tid][1];
        s0 = w * g_red[tid][2];
        s1 = w * g_red[tid][3];
    }
    r0[tid] = se; r1[tid] = s0; r2[tid] = s1;
    __syncthreads();
    for (int s = 128; s > 0; s >>= 1) {
        if (tid < s) {
            r0[tid] += r0[tid + s];
            r1[tid] += r1[tid + s];
            r2[tid] += r2[tid + s];
        }
        __syncthreads();
    }
    if (tid == 0) {
        preds[0] = r1[0] / r0[0];
        preds[1] = r2[0] / r0[0];
    }
}

// ---------------------------------------------------------------------------
// top-8 / bottom-8 via per-thread sorted lists + bitonic merge tree
// ---------------------------------------------------------------------------
__device__ __forceinline__ bool tk_better(float v1, int i1, float v2, int i2, bool mx)
{
    if (mx) return (v1 > v2) || (v1 == v2 && i1 < i2);
    return (v1 < v2) || (v1 == v2 && i1 < i2);
}

__global__ __launch_bounds__(512) void topk_kernel(const float* __restrict__ Araw)
{
    __shared__ float pv[512 * 8];
    __shared__ int   pi[512 * 8];
    int tid = threadIdx.x;

    for (int pass = 0; pass < 2; pass++) {
        bool mx = (pass == 0);
        float tv[8];
        int   ti[8];
        float pad = mx ? -INFINITY : INFINITY;
#pragma unroll
        for (int j = 0; j < 8; j++) { tv[j] = pad; ti[j] = 0x7fffffff; }
        for (int n = tid; n < NROWS; n += 512) {
            float v = Araw[n];
            if (tk_better(v, n, tv[7], ti[7], mx)) {
                int p = 7;
#pragma unroll
                for (int q = 7; q > 0; q--) {
                    if (tk_better(v, n, tv[q - 1], ti[q - 1], mx)) {
                        tv[q] = tv[q - 1]; ti[q] = ti[q - 1]; p = q - 1;
                    }
                }
                tv[p] = v; ti[p] = n;
            }
        }
#pragma unroll
        for (int j = 0; j < 8; j++) { pv[tid * 8 + j] = tv[j]; pi[tid * 8 + j] = ti[j]; }
        __syncthreads();

        // merge tree: 512 sorted-8 lists -> 1
        for (int s = 256; s > 0; s >>= 1) {
            if (tid < s) {
                float cv[16]; int ci[16];
#pragma unroll
                for (int j = 0; j < 8; j++) {
                    cv[j] = pv[tid * 8 + j];
                    ci[j] = pi[tid * 8 + j];
                    cv[8 + j] = pv[(tid + s) * 8 + 7 - j];
                    ci[8 + j] = pi[(tid + s) * 8 + 7 - j];
                }
                // bitonic merge (better-first)
#pragma unroll
                for (int st = 8; st >= 1; st >>= 1) {
#pragma unroll
                    for (int i = 0; i < 16; i++) {
                        if (!(i & st)) {
                            int k = i | st;
                            if (tk_better(cv[k], ci[k], cv[i], ci[i], mx)) {
                                float fv = cv[i]; cv[i] = cv[k]; cv[k] = fv;
                                int   fi = ci[i]; ci[i] = ci[k]; ci[k] = fi;
                            }
                        }
                    }
                }
#pragma unroll
                for (int j = 0; j < 8; j++) { pv[tid * 8 + j] = cv[j]; pi[tid * 8 + j] = ci[j]; }
            }
            __syncthreads();
        }
        if (tid < 8) g_ids[pass * 8 + tid] = pi[tid];
        __syncthreads();
    }
}

// ---------------------------------------------------------------------------
// instance loss (16 selected rows, 1 warp each; hh from hi+lo)
// ---------------------------------------------------------------------------
__global__ __launch_bounds__(512) void loss_kernel(
    const float* __restrict__ iW, const float* __restrict__ ib,
    float* __restrict__ loss)
{
    __shared__ float ls[16];
    int w    = threadIdx.x >> 5;
    int lane = threadIdx.x & 31;
    int id   = g_ids[w];
    const __nv_bfloat16* hhi = &g_hh_hi[(size_t)id * DH];
    const __nv_bfloat16* hlo = &g_hh_lo[(size_t)id * DH];
    float c0 = 0.f, c1 = 0.f;
    for (int k = lane * 4; k < DH; k += 128) {
        uint2 ph = *(const uint2*)&hhi[k];
        uint2 pl = *(const uint2*)&hlo[k];
        float h0 = __bfloat162float(__ushort_as_bfloat16((unsigned short)(ph.x & 0xffff)))
                 + __bfloat162float(__ushort_as_bfloat16((unsigned short)(pl.x & 0xffff)));
        float h1 = __bfloat162float(__ushort_as_bfloat16((unsigned short)(ph.x >> 16)))
                 + __bfloat162float(__ushort_as_bfloat16((unsigned short)(pl.x >> 16)));
        float h2 = __bfloat162float(__ushort_as_bfloat16((unsigned short)(ph.y & 0xffff)))
                 + __bfloat162float(__ushort_as_bfloat16((unsigned short)(pl.y & 0xffff)));
        float h3 = __bfloat162float(__ushort_as_bfloat16((unsigned short)(ph.y >> 16)))
                 + __bfloat162float(__ushort_as_bfloat16((unsigned short)(pl.y >> 16)));
        float4 w0 = *(const float4*)&iW[k];
        float4 w1 = *(const float4*)&iW[DH + k];
        c0 += h0 * w0.x + h1 * w0.y + h2 * w0.z + h3 * w0.w;
        c1 += h0 * w1.x + h1 * w1.y + h2 * w1.z + h3 * w1.w;
    }
#pragma unroll
    for (int m = 16; m > 0; m >>= 1) {
        c0 += __shfl_xor_sync(0xffffffffu, c0, m);
        c1 += __shfl_xor_sync(0xffffffffu, c1, m);
    }
    if (lane == 0) {
        float l0 = c0 + ib[0], l1 = c1 + ib[1];
        float mm  = fmaxf(l0, l1);
        float lse = mm + logf(expf(l0 - mm) + expf(l1 - mm));
        float lt  = (w < KSEL) ? l1 : l0;
        ls[w] = lse - lt;
    }
    __syncthreads();
    if (threadIdx.x == 0) {
        float t = 0.f;
        for (int i = 0; i < 16; i++) t += ls[i];
        loss[0] = t / 16.f;
    }
}

// ---------------------------------------------------------------------------
extern "C" void kernel_launch(void* const* d_in, const int* in_sizes, int n_in,
                              void* d_out, int out_size)
{
    const float* h     = (const float*)d_in[0];
    const float* fcW   = (const float*)d_in[1];
    const float* fcb   = (const float*)d_in[2];
    const float* aW    = (const float*)d_in[3];
    const float* abv   = (const float*)d_in[4];
    const float* bW    = (const float*)d_in[5];
    const float* bbv   = (const float*)d_in[6];
    const float* cWv   = (const float*)d_in[7];
    const float* cbv   = (const float*)d_in[8];
    const float* clsW  = (const float*)d_in[9];
    const float* clsb  = (const float*)d_in[10];
    const float* instW = (const float*)d_in[11];
    const float* instb = (const float*)d_in[12];

    float* out   = (float*)d_out;
    float* preds = out;
    float* IS    = out + 2;
    float* Araw  = out + 2 + 2 * NROWS;
    float* loss  = out + 2 + 3 * NROWS;

    static int inited = 0;
    if (!inited) {
        cudaFuncSetAttribute(gemm_mma_kernel,
                             cudaFuncAttributeMaxDynamicSharedMemorySize, SMEM_GEMM);
        inited = 1;
    }

    __nv_bfloat16 *xhi, *xlo, *w1hi, *w1lo, *wabhi, *wablo, *hhhi, *hhlo;
    cudaGetSymbolAddress((void**)&xhi,   g_x_hi);
    cudaGetSymbolAddress((void**)&xlo,   g_x_lo);
    cudaGetSymbolAddress((void**)&w1hi,  g_w1_hi);
    cudaGetSymbolAddress((void**)&w1lo,  g_w1_lo);
    cudaGetSymbolAddress((void**)&wabhi, g_wab_hi);
    cudaGetSymbolAddress((void**)&wablo, g_wab_lo);
    cudaGetSymbolAddress((void**)&hhhi,  g_hh_hi);
    cudaGetSymbolAddress((void**)&hhlo,  g_hh_lo);

    // pre-split conversions
    {
        int n4 = NROWS * DIN / 4;
        conv_split_kernel<<<(n4 + 255) / 256, 256>>>(h, xhi, xlo, n4);
        int w4 = DH * DIN / 4;
        conv_split_kernel<<<(w4 + 255) / 256, 256>>>(fcW, w1hi, w1lo, w4);
        conv_wab_kernel<<<(DH * DH / 4 + 255) / 256, 256>>>(aW, bW);
    }

    dim3 grid(4, (NROWS + BM - 1) / BM);   // colBlock fastest -> A reuse in L2

    // gemm1: hh = relu(X @ fcW^T + fcb) -> hi/lo split + cls partials
    gemm_mma_kernel<<<grid, 256, SMEM_GEMM>>>(xhi, xlo, w1hi, w1lo, fcb,
                                              (const float*)0, (const float*)0,
                                              (const float*)0, clsW, DIN, 0);

    // gemm2 fused: partial A_raw into g_part
    gemm_mma_kernel<<<grid, 256, SMEM_GEMM>>>(hhhi, hhlo, wabhi, wablo,
                                              (const float*)0, abv, bbv, cWv,
                                              (const float*)0, DH, 1);

    post1_kernel<<<NB_POST, 256>>>(cbv, clsb, Araw, IS);

    topk_kernel<<<1, 512>>>(Araw);

    finalize_kernel<<<1, 256>>>(preds);

    loss_kernel<<<1, 512>>>(instW, instb, loss);
}

// round 8
// speedup vs baseline: 2.7923x; 1.0050x over previous
#include <cuda_runtime.h>
#include <cuda_bf16.h>
#include <math.h>
#include <stdint.h>

#define NROWS 50000
#define DIN   1024
#define DH    512
#define DA    256
#define KSEL  8
#define NB_POST 196   // ceil(50000/256)

#define BM 128
#define BN 128
#define BK 32

#define ROWB      80
#define OFF_AHI   0
#define OFF_ALO   10240
#define OFF_BHI   20480
#define OFF_BLO   30720
#define STAGEB    40960
#define SMEM_GEMM (2 * STAGEB)

// ---------------- scratch (static device allocations only) ----------------
__device__ __nv_bfloat16  g_x_hi[(size_t)NROWS * DIN];
__device__ __nv_bfloat16  g_x_lo[(size_t)NROWS * DIN];
__device__ __nv_bfloat16  g_hh_hi[(size_t)NROWS * DH];
__device__ __nv_bfloat16  g_hh_lo[(size_t)NROWS * DH];
__device__ __nv_bfloat16  g_w1_hi[(size_t)DH * DIN];
__device__ __nv_bfloat16  g_w1_lo[(size_t)DH * DIN];
__device__ __nv_bfloat16  g_wab_hi[(size_t)DH * DH];   // rows 0..255 Wa, 256..511 Wb
__device__ __nv_bfloat16  g_wab_lo[(size_t)DH * DH];
__device__ float          g_part[4][NROWS];            // A_raw partials per col-block
__device__ float          g_cls_part[4][NROWS][2];     // cls partials per col-block
__device__ float          g_red[NB_POST][4];           // {max, sum e, sum e*is0, sum e*is1}
__device__ int            g_ids[16];

// ============================ helpers ======================================
__device__ __forceinline__ uint32_t smem_u32(const void* p) {
    uint32_t a;
    asm("{ .reg .u64 t; cvta.to.shared.u64 t, %1; cvt.u32.u64 %0, t; }" : "=r"(a) : "l"(p));
    return a;
}
__device__ __forceinline__ void split2(float x, float y, uint32_t& hi, uint32_t& lo)
{
    __nv_bfloat16 hx = __float2bfloat16(x);
    __nv_bfloat16 hy = __float2bfloat16(y);
    __nv_bfloat16 lx = __float2bfloat16(x - __bfloat162float(hx));
    __nv_bfloat16 ly = __float2bfloat16(y - __bfloat162float(hy));
    hi = (uint32_t)__bfloat16_as_ushort(hx) | ((uint32_t)__bfloat16_as_ushort(hy) << 16);
    lo = (uint32_t)__bfloat16_as_ushort(lx) | ((uint32_t)__bfloat16_as_ushort(ly) << 16);
}
// NOTE: non-volatile — pure register op, let ptxas schedule/interleave
__device__ __forceinline__ void mma_bf16(float* d, const uint32_t* a, const uint32_t* b)
{
    asm("mma.sync.aligned.m16n8k16.row.col.f32.bf16.bf16.f32 "
        "{%0,%1,%2,%3}, {%4,%5,%6,%7}, {%8,%9}, {%0,%1,%2,%3};"
        : "+f"(d[0]), "+f"(d[1]), "+f"(d[2]), "+f"(d[3])
        : "r"(a[0]), "r"(a[1]), "r"(a[2]), "r"(a[3]), "r"(b[0]), "r"(b[1]));
}
#define LDSM_X4(r0, r1, r2, r3, addr) \
    asm volatile("ldmatrix.sync.aligned.m8n8.x4.shared.b16 {%0,%1,%2,%3}, [%4];" \
                 : "=r"(r0), "=r"(r1), "=r"(r2), "=r"(r3) : "r"(addr))
#define CP_ASYNC16(dst, src, sz) \
    asm volatile("cp.async.cg.shared.global [%0], [%1], 16, %2;" \
                 :: "r"(dst), "l"(src), "r"(sz))
#define CP_COMMIT()  asm volatile("cp.async.commit_group;" ::: "memory")
#define CP_WAIT(n)   asm volatile("cp.async.wait_group %0;" :: "n"(n) : "memory")

__device__ __forceinline__ float fast_sigmoid(float x) {
    return __fdividef(1.f, 1.f + __expf(-x));
}
__device__ __forceinline__ float fast_tanh(float x) {
    return __fdividef(2.f, 1.f + __expf(-2.f * x)) - 1.f;
}

// ============================ convert kernels ==============================
__global__ __launch_bounds__(256) void conv_split_kernel(
    const float* __restrict__ src, __nv_bfloat16* __restrict__ hi,
    __nv_bfloat16* __restrict__ lo, int n4)
{
    int i = blockIdx.x * blockDim.x + threadIdx.x;
    if (i >= n4) return;
    float4 v = ((const float4*)src)[i];
    uint32_t h0, l0, h1, l1;
    split2(v.x, v.y, h0, l0);
    split2(v.z, v.w, h1, l1);
    ((uint2*)hi)[i] = make_uint2(h0, h1);
    ((uint2*)lo)[i] = make_uint2(l0, l1);
}

__global__ __launch_bounds__(256) void conv_wab_kernel(
    const float* __restrict__ Wa, const float* __restrict__ Wb)
{
    int i = blockIdx.x * blockDim.x + threadIdx.x;
    if (i >= DH * DH / 4) return;
    int elem = i * 4;
    int row = elem / DH;
    int col = elem % DH;
    const float* src = (row < DA) ? &Wa[(size_t)row * DH + col]
                                  : &Wb[(size_t)(row - DA) * DH + col];
    float4 v = *(const float4*)src;
    uint32_t h0, l0, h1, l1;
    split2(v.x, v.y, h0, l0);
    split2(v.z, v.w, h1, l1);
    ((uint2*)g_wab_hi)[i] = make_uint2(h0, h1);
    ((uint2*)g_wab_lo)[i] = make_uint2(l0, l1);
}

// ===========================================================================
// 3xBF16 split GEMM (mma.sync + ldmatrix + cp.async double buffer)
//  grid = (colBlocks, rowBlocks): consecutive CTAs share the A tile -> L2 reuse
//  mode 0 (gemm1): relu(A@B^T + bias) -> hh hi/lo split + cls partials
//  mode 1 (gemm2): fused A_raw partial reduction -> g_part
// ===========================================================================
__global__ __launch_bounds__(256, 2) void gemm_mma_kernel(
    const __nv_bfloat16* __restrict__ Ahi, const __nv_bfloat16* __restrict__ Alo,
    const __nv_bfloat16* __restrict__ Bhi, const __nv_bfloat16* __restrict__ Blo,
    const float* __restrict__ bias,
    const float* __restrict__ abv, const float* __restrict__ bbv,
    const float* __restrict__ cWv, const float* __restrict__ clsW,
    int K, int mode)
{
    extern __shared__ char smem[];
    const uint32_t sbase = smem_u32(smem);

    const int tid    = threadIdx.x;
    const int wid    = tid >> 5;
    const int lane   = tid & 31;
    const int warp_m = wid & 1;
    const int warp_n = wid >> 1;
    const int g      = lane >> 2;
    const int t      = lane & 3;
    const int bx     = blockIdx.x;                  // column block (fastest)
    const int row0   = blockIdx.y * BM;
    const int col0   = (mode == 0) ? bx * BN : bx * 64;

    const int mat   = lane >> 3;
    const int rowin = lane & 7;
    const int rowA  = warp_m * 64 + ((mat & 1) << 3) + rowin;
    const int kA    = (mat >> 1) << 3;
    const int rowB0 = warp_n * 32 + ((mat >> 1) << 3) + rowin;
    const int kB    = (mat & 1) << 3;

    const int frow = tid >> 2;
    const int fseg = (tid & 3) * 16;

    float acc[4][4][4];
#pragma unroll
    for (int mt = 0; mt < 4; mt++)
#pragma unroll
        for (int nt = 0; nt < 4; nt++)
#pragma unroll
            for (int e = 0; e < 4; e++) acc[mt][nt][e] = 0.f;

    const int KT = K / BK;

    auto fill = [&](int kt, int s) {
        uint32_t sb = sbase + s * STAGEB;
        int kc = kt * BK + (fseg >> 1);
#pragma unroll
        for (int i = 0; i < 2; i++) {
            int r = frow + 64 * i;
            int gr = row0 + r;
            uint32_t ok = (gr < NROWS) ? 16u : 0u;
            size_t gi = (size_t)min(gr, NROWS - 1) * K + kc;
            uint32_t d = sb + r * ROWB + fseg;
            CP_ASYNC16(d + OFF_AHI, (const char*)&Ahi[gi], ok);
            CP_ASYNC16(d + OFF_ALO, (const char*)&Alo[gi], ok);
            int brow;
            if (mode == 0) {
                brow = col0 + r;
            } else {
                int w = r >> 5, ii = r & 31;
                int j = col0 + (w << 4) + (ii & 15);
                brow = (ii < 16) ? j : j + DA;
            }
            size_t bi = (size_t)brow * K + kc;
            CP_ASYNC16(d + OFF_BHI, (const char*)&Bhi[bi], 16u);
            CP_ASYNC16(d + OFF_BLO, (const char*)&Blo[bi], 16u);
        }
    };

    fill(0, 0);
    CP_COMMIT();

    for (int kt = 0; kt < KT; kt++) {
        int cur = kt & 1;
        if (kt + 1 < KT) {
            fill(kt + 1, cur ^ 1);
            CP_COMMIT();
            CP_WAIT(1);
        } else {
            CP_WAIT(0);
        }
        __syncthreads();

        uint32_t sb = sbase + cur * STAGEB;
#pragma unroll
        for (int ks = 0; ks < BK; ks += 16) {
            uint32_t bh[4][2], bl[4][2];
#pragma unroll
            for (int p = 0; p < 2; p++) {
                uint32_t ab_ = sb + (rowB0 + p * 16) * ROWB + (ks + kB) * 2;
                LDSM_X4(bh[2 * p][0], bh[2 * p][1], bh[2 * p + 1][0], bh[2 * p + 1][1],
                        ab_ + OFF_BHI);
                LDSM_X4(bl[2 * p][0], bl[2 * p][1], bl[2 * p + 1][0], bl[2 * p + 1][1],
                        ab_ + OFF_BLO);
            }
#pragma unroll
            for (int mt = 0; mt < 4; mt++) {
                uint32_t aa = sb + (rowA + mt * 16) * ROWB + (ks + kA) * 2;
                uint32_t ah[4], al[4];
                LDSM_X4(ah[0], ah[1], ah[2], ah[3], aa + OFF_AHI);
                LDSM_X4(al[0], al[1], al[2], al[3], aa + OFF_ALO);
                // product-major passes: same-acc MMAs are 4 issues apart
#pragma unroll
                for (int nt = 0; nt < 4; nt++) mma_bf16(acc[mt][nt], ah, bh[nt]);
#pragma unroll
                for (int nt = 0; nt < 4; nt++) mma_bf16(acc[mt][nt], ah, bl[nt]);
#pragma unroll
                for (int nt = 0; nt < 4; nt++) mma_bf16(acc[mt][nt], al, bh[nt]);
            }
        }
        __syncthreads();
    }

    if (mode == 0) {
        // ---- gemm1 epilogue: relu(C+bias) -> hh hi/lo split + cls partials ----
        float* sc0 = (float*)smem;           // [128][4]
        float* sc1 = (float*)smem + 512;     // [128][4]
#pragma unroll
        for (int mt = 0; mt < 4; mt++) {
            int r0 = row0 + warp_m * 64 + mt * 16 + g;
            int r1 = r0 + 8;
            float p00 = 0.f, p01 = 0.f, p10 = 0.f, p11 = 0.f;
#pragma unroll
            for (int nt = 0; nt < 4; nt++) {
                int c = col0 + warp_n * 32 + nt * 8 + 2 * t;
                float b0 = __ldg(&bias[c]), b1 = __ldg(&bias[c + 1]);
                float v0 = fmaxf(acc[mt][nt][0] + b0, 0.f);
                float v1 = fmaxf(acc[mt][nt][1] + b1, 0.f);
                float v2 = fmaxf(acc[mt][nt][2] + b0, 0.f);
                float v3 = fmaxf(acc[mt][nt][3] + b1, 0.f);
                float w00 = __ldg(&clsW[c]),      w01 = __ldg(&clsW[c + 1]);
                float w10 = __ldg(&clsW[DH + c]), w11 = __ldg(&clsW[DH + c + 1]);
                p00 += v0 * w00 + v1 * w01;
                p01 += v0 * w10 + v1 * w11;
                p10 += v2 * w00 + v3 * w01;
                p11 += v2 * w10 + v3 * w11;
                uint32_t hh, ll;
                if (r0 < NROWS) {
                    split2(v0, v1, hh, ll);
                    *(uint32_t*)&g_hh_hi[(size_t)r0 * DH + c] = hh;
                    *(uint32_t*)&g_hh_lo[(size_t)r0 * DH + c] = ll;
                }
                if (r1 < NROWS) {
                    split2(v2, v3, hh, ll);
                    *(uint32_t*)&g_hh_hi[(size_t)r1 * DH + c] = hh;
                    *(uint32_t*)&g_hh_lo[(size_t)r1 * DH + c] = ll;
                }
            }
            p00 += __shfl_xor_sync(0xffffffffu, p00, 1);
            p00 += __shfl_xor_sync(0xffffffffu, p00, 2);
            p01 += __shfl_xor_sync(0xffffffffu, p01, 1);
            p01 += __shfl_xor_sync(0xffffffffu, p01, 2);
            p10 += __shfl_xor_sync(0xffffffffu, p10, 1);
            p10 += __shfl_xor_sync(0xffffffffu, p10, 2);
            p11 += __shfl_xor_sync(0xffffffffu, p11, 1);
            p11 += __shfl_xor_sync(0xffffffffu, p11, 2);
            if (t == 0) {
                int rl = warp_m * 64 + mt * 16 + g;
                sc0[rl * 4 + warp_n] = p00;
                sc1[rl * 4 + warp_n] = p01;
                sc0[(rl + 8) * 4 + warp_n] = p10;
                sc1[(rl + 8) * 4 + warp_n] = p11;
            }
        }
        __syncthreads();
        if (tid < 128) {
            int grow = row0 + tid;
            if (grow < NROWS) {
                g_cls_part[bx][grow][0] = sc0[tid * 4 + 0] + sc0[tid * 4 + 1] +
                                          sc0[tid * 4 + 2] + sc0[tid * 4 + 3];
                g_cls_part[bx][grow][1] = sc1[tid * 4 + 0] + sc1[tid * 4 + 1] +
                                          sc1[tid * 4 + 2] + sc1[tid * 4 + 3];
            }
        }
    } else {
        // ---- gemm2 fused epilogue: partial A_raw reduction ----
        float* spart = (float*)smem;   // [128][4]
#pragma unroll
        for (int mt = 0; mt < 4; mt++) {
            float s0 = 0.f, s1 = 0.f;
#pragma unroll
            for (int nt = 0; nt < 2; nt++) {
                int j = col0 + warp_n * 16 + nt * 8 + 2 * t;
                float ab0 = __ldg(&abv[j]), ab1 = __ldg(&abv[j + 1]);
                float bb0 = __ldg(&bbv[j]), bb1 = __ldg(&bbv[j + 1]);
                float c0  = __ldg(&cWv[j]), c1  = __ldg(&cWv[j + 1]);
                s0 += c0 * fast_tanh(acc[mt][nt][0] + ab0) * fast_sigmoid(acc[mt][nt + 2][0] + bb0);
                s0 += c1 * fast_tanh(acc[mt][nt][1] + ab1) * fast_sigmoid(acc[mt][nt + 2][1] + bb1);
                s1 += c0 * fast_tanh(acc[mt][nt][2] + ab0) * fast_sigmoid(acc[mt][nt + 2][2] + bb0);
                s1 += c1 * fast_tanh(acc[mt][nt][3] + ab1) * fast_sigmoid(acc[mt][nt + 2][3] + bb1);
            }
            s0 += __shfl_xor_sync(0xffffffffu, s0, 1);
            s0 += __shfl_xor_sync(0xffffffffu, s0, 2);
            s1 += __shfl_xor_sync(0xffffffffu, s1, 1);
            s1 += __shfl_xor_sync(0xffffffffu, s1, 2);
            if (t == 0) {
                int rl = warp_m * 64 + mt * 16 + g;
                spart[rl * 4 + warp_n] = s0;
                spart[(rl + 8) * 4 + warp_n] = s1;
            }
        }
        __syncthreads();
        if (tid < 128) {
            int grow = row0 + tid;
            if (grow < NROWS) {
                g_part[bx][grow] = spart[tid * 4 + 0] + spart[tid * 4 + 1] +
                                   spart[tid * 4 + 2] + spart[tid * 4 + 3];
            }
        }
    }
}

// ---------------------------------------------------------------------------
// post1: Araw + IS finalize + per-block softmax partials (deterministic)
// ---------------------------------------------------------------------------
__global__ __launch_bounds__(256) void post1_kernel(
    const float* __restrict__ cb, const float* __restrict__ clsb,
    float* __restrict__ Araw, float* __restrict__ IS)
{
    __shared__ float rm[256], r0[256], r1[256], r2[256];
    int tid = threadIdx.x;
    int n   = blockIdx.x * 256 + tid;
    bool valid = (n < NROWS);

    float a = -INFINITY, is0 = 0.f, is1 = 0.f;
    if (valid) {
        a = cb[0] + g_part[0][n] + g_part[1][n] + g_part[2][n] + g_part[3][n];
        Araw[n] = a;
        is0 = clsb[0] + g_cls_part[0][n][0] + g_cls_part[1][n][0] +
                        g_cls_part[2][n][0] + g_cls_part[3][n][0];
        is1 = clsb[1] + g_cls_part[0][n][1] + g_cls_part[1][n][1] +
                        g_cls_part[2][n][1] + g_cls_part[3][n][1];
        IS[(size_t)n * 2 + 0] = is0;
        IS[(size_t)n * 2 + 1] = is1;
    }

    rm[tid] = a;
    __syncthreads();
    for (int s = 128; s > 0; s >>= 1) {
        if (tid < s) rm[tid] = fmaxf(rm[tid], rm[tid + s]);
        __syncthreads();
    }
    float m = rm[0];
    __syncthreads();

    float e = valid ? expf(a - m) : 0.f;
    r0[tid] = e; r1[tid] = e * is0; r2[tid] = e * is1;
    __syncthreads();
    for (int s = 128; s > 0; s >>= 1) {
        if (tid < s) {
            r0[tid] += r0[tid + s];
            r1[tid] += r1[tid + s];
            r2[tid] += r2[tid + s];
        }
        __syncthreads();
    }
    if (tid == 0) {
        g_red[blockIdx.x][0] = m;
        g_red[blockIdx.x][1] = r0[0];
        g_red[blockIdx.x][2] = r1[0];
        g_red[blockIdx.x][3] = r2[0];
    }
}

// ---------------------------------------------------------------------------
// finalize: combine block partials -> preds
// ---------------------------------------------------------------------------
__global__ __launch_bounds__(256) void finalize_kernel(float* __restrict__ preds)
{
    __shared__ float rm[256], r0[256], r1[256], r2[256];
    int tid = threadIdx.x;
    float m = (tid < NB_POST) ? g_red[tid][0] : -INFINITY;
    rm[tid] = m;
    __syncthreads();
    for (int s = 128; s > 0; s >>= 1) {
        if (tid < s) rm[tid] = fmaxf(rm[tid], rm[tid + s]);
        __syncthreads();
    }
    float M = rm[0];
    __syncthreads();
    float se = 0.f, s0 = 0.f, s1 = 0.f;
    if (tid < NB_POST) {
        float w = expf(g_red[tid][0] - M);
        se = w * g_red[tid][1];
        s0 = w * g_red[tid][2];
        s1 = w * g_red[tid][3];
    }
    r0[tid] = se; r1[tid] = s0; r2[tid] = s1;
    __syncthreads();
    for (int s = 128; s > 0; s >>= 1) {
        if (tid < s) {
            r0[tid] += r0[tid + s];
            r1[tid] += r1[tid + s];
            r2[tid] += r2[tid + s];
        }
        __syncthreads();
    }
    if (tid == 0) {
        preds[0] = r1[0] / r0[0];
        preds[1] = r2[0] / r0[0];
    }
}

// ---------------------------------------------------------------------------
// top-8 / bottom-8 via per-thread sorted lists + bitonic merge tree
// ---------------------------------------------------------------------------
__device__ __forceinline__ bool tk_better(float v1, int i1, float v2, int i2, bool mx)
{
    if (mx) return (v1 > v2) || (v1 == v2 && i1 < i2);
    return (v1 < v2) || (v1 == v2 && i1 < i2);
}

__global__ __launch_bounds__(512) void topk_kernel(const float* __restrict__ Araw)
{
    __shared__ float pv[512 * 8];
    __shared__ int   pi[512 * 8];
    int tid = threadIdx.x;

    for (int pass = 0; pass < 2; pass++) {
        bool mx = (pass == 0);
        float tv[8];
        int   ti[8];
        float pad = mx ? -INFINITY : INFINITY;
#pragma unroll
        for (int j = 0; j < 8; j++) { tv[j] = pad; ti[j] = 0x7fffffff; }
        for (int n = tid; n < NROWS; n += 512) {
            float v = Araw[n];
            if (tk_better(v, n, tv[7], ti[7], mx)) {
                int p = 7;
#pragma unroll
                for (int q = 7; q > 0; q--) {
                    if (tk_better(v, n, tv[q - 1], ti[q - 1], mx)) {
                        tv[q] = tv[q - 1]; ti[q] = ti[q - 1]; p = q - 1;
                    }
                }
                tv[p] = v; ti[p] = n;
            }
        }
#pragma unroll
        for (int j = 0; j < 8; j++) { pv[tid * 8 + j] = tv[j]; pi[tid * 8 + j] = ti[j]; }
        __syncthreads();

        // merge tree: 512 sorted-8 lists -> 1
        for (int s = 256; s > 0; s >>= 1) {
            if (tid < s) {
                float cv[16]; int ci[16];
#pragma unroll
                for (int j = 0; j < 8; j++) {
                    cv[j] = pv[tid * 8 + j];
                    ci[j] = pi[tid * 8 + j];
                    cv[8 + j] = pv[(tid + s) * 8 + 7 - j];
                    ci[8 + j] = pi[(tid + s) * 8 + 7 - j];
                }
#pragma unroll
                for (int st = 8; st >= 1; st >>= 1) {
#pragma unroll
                    for (int i = 0; i < 16; i++) {
                        if (!(i & st)) {
                            int k = i | st;
                            if (tk_better(cv[k], ci[k], cv[i], ci[i], mx)) {
                                float fv = cv[i]; cv[i] = cv[k]; cv[k] = fv;
                                int   fi = ci[i]; ci[i] = ci[k]; ci[k] = fi;
                            }
                        }
                    }
                }
#pragma unroll
                for (int j = 0; j < 8; j++) { pv[tid * 8 + j] = cv[j]; pi[tid * 8 + j] = ci[j]; }
            }
            __syncthreads();
        }
        if (tid < 8) g_ids[pass * 8 + tid] = pi[tid];
        __syncthreads();
    }
}

// ---------------------------------------------------------------------------
// instance loss (16 selected rows, 1 warp each; hh from hi+lo)
// ---------------------------------------------------------------------------
__global__ __launch_bounds__(512) void loss_kernel(
    const float* __restrict__ iW, const float* __restrict__ ib,
    float* __restrict__ loss)
{
    __shared__ float ls[16];
    int w    = threadIdx.x >> 5;
    int lane = threadIdx.x & 31;
    int id   = g_ids[w];
    const __nv_bfloat16* hhi = &g_hh_hi[(size_t)id * DH];
    const __nv_bfloat16* hlo = &g_hh_lo[(size_t)id * DH];
    float c0 = 0.f, c1 = 0.f;
    for (int k = lane * 4; k < DH; k += 128) {
        uint2 ph = *(const uint2*)&hhi[k];
        uint2 pl = *(const uint2*)&hlo[k];
        float h0 = __bfloat162float(__ushort_as_bfloat16((unsigned short)(ph.x & 0xffff)))
                 + __bfloat162float(__ushort_as_bfloat16((unsigned short)(pl.x & 0xffff)));
        float h1 = __bfloat162float(__ushort_as_bfloat16((unsigned short)(ph.x >> 16)))
                 + __bfloat162float(__ushort_as_bfloat16((unsigned short)(pl.x >> 16)));
        float h2 = __bfloat162float(__ushort_as_bfloat16((unsigned short)(ph.y & 0xffff)))
                 + __bfloat162float(__ushort_as_bfloat16((unsigned short)(pl.y & 0xffff)));
        float h3 = __bfloat162float(__ushort_as_bfloat16((unsigned short)(ph.y >> 16)))
                 + __bfloat162float(__ushort_as_bfloat16((unsigned short)(pl.y >> 16)));
        float4 w0 = *(const float4*)&iW[k];
        float4 w1 = *(const float4*)&iW[DH + k];
        c0 += h0 * w0.x + h1 * w0.y + h2 * w0.z + h3 * w0.w;
        c1 += h0 * w1.x + h1 * w1.y + h2 * w1.z + h3 * w1.w;
    }
#pragma unroll
    for (int m = 16; m > 0; m >>= 1) {
        c0 += __shfl_xor_sync(0xffffffffu, c0, m);
        c1 += __shfl_xor_sync(0xffffffffu, c1, m);
    }
    if (lane == 0) {
        float l0 = c0 + ib[0], l1 = c1 + ib[1];
        float mm  = fmaxf(l0, l1);
        float lse = mm + logf(expf(l0 - mm) + expf(l1 - mm));
        float lt  = (w < KSEL) ? l1 : l0;
        ls[w] = lse - lt;
    }
    __syncthreads();
    if (threadIdx.x == 0) {
        float t = 0.f;
        for (int i = 0; i < 16; i++) t += ls[i];
        loss[0] = t / 16.f;
    }
}

// ---------------------------------------------------------------------------
extern "C" void kernel_launch(void* const* d_in, const int* in_sizes, int n_in,
                              void* d_out, int out_size)
{
    const float* h     = (const float*)d_in[0];
    const float* fcW   = (const float*)d_in[1];
    const float* fcb   = (const float*)d_in[2];
    const float* aW    = (const float*)d_in[3];
    const float* abv   = (const float*)d_in[4];
    const float* bW    = (const float*)d_in[5];
    const float* bbv   = (const float*)d_in[6];
    const float* cWv   = (const float*)d_in[7];
    const float* cbv   = (const float*)d_in[8];
    const float* clsW  = (const float*)d_in[9];
    const float* clsb  = (const float*)d_in[10];
    const float* instW = (const float*)d_in[11];
    const float* instb = (const float*)d_in[12];

    float* out   = (float*)d_out;
    float* preds = out;
    float* IS    = out + 2;
    float* Araw  = out + 2 + 2 * NROWS;
    float* loss  = out + 2 + 3 * NROWS;

    static int inited = 0;
    if (!inited) {
        cudaFuncSetAttribute(gemm_mma_kernel,
                             cudaFuncAttributeMaxDynamicSharedMemorySize, SMEM_GEMM);
        inited = 1;
    }

    __nv_bfloat16 *xhi, *xlo, *w1hi, *w1lo, *wabhi, *wablo, *hhhi, *hhlo;
    cudaGetSymbolAddress((void**)&xhi,   g_x_hi);
    cudaGetSymbolAddress((void**)&xlo,   g_x_lo);
    cudaGetSymbolAddress((void**)&w1hi,  g_w1_hi);
    cudaGetSymbolAddress((void**)&w1lo,  g_w1_lo);
    cudaGetSymbolAddress((void**)&wabhi, g_wab_hi);
    cudaGetSymbolAddress((void**)&wablo, g_wab_lo);
    cudaGetSymbolAddress((void**)&hhhi,  g_hh_hi);
    cudaGetSymbolAddress((void**)&hhlo,  g_hh_lo);

    // pre-split conversions
    {
        int n4 = NROWS * DIN / 4;
        conv_split_kernel<<<(n4 + 255) / 256, 256>>>(h, xhi, xlo, n4);
        int w4 = DH * DIN / 4;
        conv_split_kernel<<<(w4 + 255) / 256, 256>>>(fcW, w1hi, w1lo, w4);
        conv_wab_kernel<<<(DH * DH / 4 + 255) / 256, 256>>>(aW, bW);
    }

    dim3 grid(4, (NROWS + BM - 1) / BM);   // colBlock fastest -> A reuse in L2

    // gemm1: hh = relu(X @ fcW^T + fcb) -> hi/lo split + cls partials
    gemm_mma_kernel<<<grid, 256, SMEM_GEMM>>>(xhi, xlo, w1hi, w1lo, fcb,
                                              (const float*)0, (const float*)0,
                                              (const float*)0, clsW, DIN, 0);

    // gemm2 fused: partial A_raw into g_part
    gemm_mma_kernel<<<grid, 256, SMEM_GEMM>>>(hhhi, hhlo, wabhi, wablo,
                                              (const float*)0, abv, bbv, cWv,
                                              (const float*)0, DH, 1);

    post1_kernel<<<NB_POST, 256>>>(cbv, clsb, Araw, IS);

    topk_kernel<<<1, 512>>>(Araw);

    finalize_kernel<<<1, 256>>>(preds);

    loss_kernel<<<1, 512>>>(instW, instb, loss);
}